// round 1
// baseline (speedup 1.0000x reference)
#include <cuda_runtime.h>
#include <cuda_bf16.h>
#include <math.h>

// ---------------- Problem constants ----------------
#define T_SEQ   2048
#define NEMBD   2048
#define NHEAD   16
#define KVLOW   512
#define QLOW    1024
#define ROPEHS  64
#define QKHS    576          // KVLOW + ROPEHS
#define LATD    1600         // KVLOW + ROPEHS + QLOW
#define QTOT    9216         // NHEAD * QKHS
#define YTOT    8192         // NHEAD * KVLOW

// ---------------- Scratch (device globals; no allocations allowed) ----------------
__device__ float g_lat[(size_t)T_SEQ * LATD];        // latents [t][1600]
__device__ float g_qbuf[(size_t)T_SEQ * QTOT];       // q [t][h*576+j]
__device__ float g_kmat[(size_t)T_SEQ * QKHS];       // k [s][576]  (v = first 512 cols of g_lat rows)
__device__ float g_scores[(size_t)NHEAD * T_SEQ * T_SEQ]; // per-head scores/attn
__device__ float g_y[(size_t)T_SEQ * YTOT];          // y [t][h*512+d]

// ---------------- SGEMM: C = alpha * A*B (or A*B^T), fp32 ----------------
// 128x128 block tile, BK=8, 256 threads, 8x8 per-thread register tile.
#define BM 128
#define BN 128
#define BK 8
#define TM 8
#define TN 8

template<bool TRANSB, bool CAUSAL_SKIP, bool CAUSAL_K>
__global__ __launch_bounds__(256)
void sgemm_kernel(const float* __restrict__ A, const float* __restrict__ B,
                  float* __restrict__ C,
                  int M, int N, int K,
                  int lda, int ldb, int ldc,
                  long sA, long sB, long sC,
                  float alpha)
{
    const int bx = blockIdx.x, by = blockIdx.y, bz = blockIdx.z;
    if (CAUSAL_SKIP && bx > by) return;   // tile fully above the diagonal

    A += (long)bz * sA;
    B += (long)bz * sB;
    C += (long)bz * sC;

    const int Keff = CAUSAL_K ? min(K, (by + 1) * BM) : K;

    __shared__ float As[BK][BM];
    __shared__ float Bs[BK][BN + 4];

    const int tid = threadIdx.x;
    const int tx = tid & 15;      // 0..15 -> 8 cols each
    const int ty = tid >> 4;      // 0..15 -> 8 rows each
    const int m0 = by * BM, n0 = bx * BN;

    float acc[TM][TN];
    #pragma unroll
    for (int i = 0; i < TM; i++)
        #pragma unroll
        for (int j = 0; j < TN; j++)
            acc[i][j] = 0.f;

    // load mapping
    const int arow = tid >> 1;            // 0..127 (m within tile)
    const int acol = (tid & 1) * 4;       // 0 or 4 (k within tile)
    const int brow_nn = tid >> 5;         // 0..7   (k)
    const int bcol_nn = (tid & 31) * 4;   // 0..124 (n)
    const int brow_nt = tid >> 1;         // 0..127 (n)
    const int bcol_nt = (tid & 1) * 4;    // 0 or 4 (k)

    for (int k0 = 0; k0 < Keff; k0 += BK) {
        // --- A tile: As[k][m] = A[m0+arow][k0+acol+i]
        {
            const int m = m0 + arow;
            const bool okm = (m < M);
            const float* ap = A + (long)m * lda + (k0 + acol);
            #pragma unroll
            for (int i = 0; i < 4; i++)
                As[acol + i][arow] = okm ? ap[i] : 0.f;
        }
        // --- B tile
        if (!TRANSB) {
            const int kk = k0 + brow_nn;
            const float* bp = B + (long)kk * ldb + (n0 + bcol_nn);
            #pragma unroll
            for (int i = 0; i < 4; i++) {
                const int n = n0 + bcol_nn + i;
                Bs[brow_nn][bcol_nn + i] = (n < N) ? bp[i] : 0.f;
            }
        } else {
            const int n = n0 + brow_nt;
            const bool okn = (n < N);
            const float* bp = B + (long)n * ldb + (k0 + bcol_nt);
            #pragma unroll
            for (int i = 0; i < 4; i++)
                Bs[bcol_nt + i][brow_nt] = okn ? bp[i] : 0.f;
        }
        __syncthreads();

        #pragma unroll
        for (int kk = 0; kk < BK; kk++) {
            float a[TM], b[TN];
            #pragma unroll
            for (int i = 0; i < TM; i++) a[i] = As[kk][ty * TM + i];
            #pragma unroll
            for (int j = 0; j < TN; j++) b[j] = Bs[kk][tx * TN + j];
            #pragma unroll
            for (int i = 0; i < TM; i++)
                #pragma unroll
                for (int j = 0; j < TN; j++)
                    acc[i][j] += a[i] * b[j];
        }
        __syncthreads();
    }

    #pragma unroll
    for (int i = 0; i < TM; i++) {
        const int m = m0 + ty * TM + i;
        if (m >= M) continue;
        float* cp = C + (long)m * ldc;
        #pragma unroll
        for (int j = 0; j < TN; j++) {
            const int n = n0 + tx * TN + j;
            if (n < N) cp[n] = acc[i][j] * alpha;
        }
    }
}

// ---------------- RoPE + K assembly ----------------
// One block per token t (256 threads):
//   kmat[t][0:512]   = lat[t][0:512]
//   kmat[t][512:576] = rope(lat[t][512:576], cos[t], sin[t])
//   qbuf[t][h*576+512 : h*576+576] = rope(same), in place, for all 16 heads
__global__ void rope_build_kernel(const float* __restrict__ lat,
                                  float* __restrict__ qbuf,
                                  float* __restrict__ kmat,
                                  const float* __restrict__ cosT,
                                  const float* __restrict__ sinT)
{
    const int t = blockIdx.x;
    const int tid = threadIdx.x;
    const float* l = lat + (long)t * LATD;
    float* km = kmat + (long)t * QKHS;

    __shared__ float cs[ROPEHS], sn[ROPEHS];
    if (tid < ROPEHS) {
        cs[tid] = cosT[(long)t * ROPEHS + tid];
        sn[tid] = sinT[(long)t * ROPEHS + tid];
    }

    // copy c_kv
    for (int i = tid; i < KVLOW; i += 256)
        km[i] = l[i];

    __syncthreads();

    // rope k_r
    if (tid < ROPEHS) {
        const float xv = l[KVLOW + tid];
        const float pv = (tid < 32) ? l[KVLOW + tid + 32] : l[KVLOW + tid - 32];
        const float rot = (tid < 32) ? -pv : pv;
        km[KVLOW + tid] = xv * cs[tid] + rot * sn[tid];
    }

    // rope q (16 heads x 64 dims = 1024 elems, in place): read-all then write-all
    float xv[4], pv[4];
    #pragma unroll
    for (int r = 0; r < 4; r++) {
        const int idx = tid + r * 256;      // 0..1023
        const int h = idx >> 6, i = idx & 63;
        const float* qp = qbuf + (long)t * QTOT + h * QKHS + KVLOW;
        xv[r] = qp[i];
        pv[r] = (i < 32) ? qp[i + 32] : qp[i - 32];
    }
    __syncthreads();
    #pragma unroll
    for (int r = 0; r < 4; r++) {
        const int idx = tid + r * 256;
        const int h = idx >> 6, i = idx & 63;
        float* qp = qbuf + (long)t * QTOT + h * QKHS + KVLOW;
        const float rot = (i < 32) ? -pv[r] : pv[r];
        qp[i] = xv[r] * cs[i] + rot * sn[i];
    }
}

// ---------------- Row softmax (causal), smem-resident row ----------------
// Block per (t, h). Normalizes scores[h][t][0:t+1], zero-fills (t, kpad) so
// the PV GEMM can run K up to the diagonal tile boundary.
__global__ __launch_bounds__(256)
void softmax_kernel(float* __restrict__ scores)
{
    __shared__ float srow[T_SEQ];
    __shared__ float red[8];
    const int t = blockIdx.x, h = blockIdx.y;
    const int tid = threadIdx.x;
    float* row = scores + ((size_t)h * T_SEQ + t) * T_SEQ;
    const int n = t + 1;

    float m = -3.4e38f;
    for (int s = tid; s < n; s += 256) {
        const float v = row[s];
        srow[s] = v;
        m = fmaxf(m, v);
    }
    // block max
    #pragma unroll
    for (int o = 16; o; o >>= 1) m = fmaxf(m, __shfl_xor_sync(0xffffffffu, m, o));
    if ((tid & 31) == 0) red[tid >> 5] = m;
    __syncthreads();
    float mmax = red[0];
    #pragma unroll
    for (int i = 1; i < 8; i++) mmax = fmaxf(mmax, red[i]);
    __syncthreads();

    float sum = 0.f;
    for (int s = tid; s < n; s += 256) {
        const float e = __expf(srow[s] - mmax);
        srow[s] = e;
        sum += e;
    }
    #pragma unroll
    for (int o = 16; o; o >>= 1) sum += __shfl_xor_sync(0xffffffffu, sum, o);
    if ((tid & 31) == 0) red[tid >> 5] = sum;
    __syncthreads();
    float total = 0.f;
    #pragma unroll
    for (int i = 0; i < 8; i++) total += red[i];
    const float inv = 1.f / total;

    for (int s = tid; s < n; s += 256)
        row[s] = srow[s] * inv;

    const int kpad = ((t >> 7) + 1) << 7;   // diagonal-tile boundary
    for (int s = n + tid; s < kpad; s += 256)
        row[s] = 0.f;
}

// ---------------- Launch ----------------
extern "C" void kernel_launch(void* const* d_in, const int* in_sizes, int n_in,
                              void* d_out, int out_size)
{
    (void)in_sizes; (void)n_in; (void)out_size;
    const float* x     = (const float*)d_in[0];
    const float* cosT  = (const float*)d_in[1];
    const float* sinT  = (const float*)d_in[2];
    const float* Wqkv  = (const float*)d_in[3];
    const float* Wqdec = (const float*)d_in[4];
    const float* Wout  = (const float*)d_in[5];
    float* out = (float*)d_out;

    float *lat, *qbuf, *kmat, *scores, *y;
    cudaGetSymbolAddress((void**)&lat,    g_lat);
    cudaGetSymbolAddress((void**)&qbuf,   g_qbuf);
    cudaGetSymbolAddress((void**)&kmat,   g_kmat);
    cudaGetSymbolAddress((void**)&scores, g_scores);
    cudaGetSymbolAddress((void**)&y,      g_y);

    const dim3 blk(256);
    const float scale = 0.04419417382415922f;   // 1/sqrt(512)

    // 1) latents = x @ W_qkv : [2048,2048]x[2048,1600]
    sgemm_kernel<false, false, false><<<dim3(13, 16, 1), blk>>>(
        x, Wqkv, lat, T_SEQ, LATD, NEMBD, NEMBD, LATD, LATD, 0, 0, 0, 1.f);

    // 2) q = c_q @ W_qdec : [2048,1024]x[1024,9216]
    sgemm_kernel<false, false, false><<<dim3(72, 16, 1), blk>>>(
        lat + (KVLOW + ROPEHS), Wqdec, qbuf, T_SEQ, QTOT, QLOW,
        LATD, QTOT, QTOT, 0, 0, 0, 1.f);

    // 3) RoPE + K assembly
    rope_build_kernel<<<T_SEQ, 256>>>(lat, qbuf, kmat, cosT, sinT);

    // 4) scores[h] = scale * q_h @ k^T : [2048,576]x[576,2048], causal tile skip
    sgemm_kernel<true, true, false><<<dim3(16, 16, NHEAD), blk>>>(
        qbuf, kmat, scores, T_SEQ, T_SEQ, QKHS,
        QTOT, QKHS, T_SEQ,
        (long)QKHS, 0, (long)T_SEQ * T_SEQ, scale);

    // 5) causal softmax
    softmax_kernel<<<dim3(T_SEQ, NHEAD), 256>>>(scores);

    // 6) y[h] = attn_h @ v : [2048,(causal K)]x[*,512], v = lat[:, :512]
    sgemm_kernel<false, false, true><<<dim3(4, 16, NHEAD), blk>>>(
        scores, lat, y, T_SEQ, KVLOW, T_SEQ,
        T_SEQ, LATD, YTOT,
        (long)T_SEQ * T_SEQ, 0, (long)KVLOW, 1.f);

    // 7) out = y @ W_out : [2048,8192]x[8192,2048]
    sgemm_kernel<false, false, false><<<dim3(16, 16, 1), blk>>>(
        y, Wout, out, T_SEQ, NEMBD, YTOT, YTOT, NEMBD, NEMBD, 0, 0, 0, 1.f);
}

// round 3
// speedup vs baseline: 2.9107x; 2.9107x over previous
#include <cuda_runtime.h>
#include <cuda_bf16.h>
#include <cstdint>

// ---------------- Problem constants ----------------
#define T_SEQ   2048
#define NEMBD   2048
#define NHEAD   16
#define KVLOW   512
#define QLOW    1024
#define ROPEHS  64
#define QKHS    576
#define LATD    1600
#define QTOT    9216
#define YTOT    8192
#define NPAD1   1664   // 1600 padded up to 13*128

typedef __nv_bfloat16 bf16;

// ---------------- Scratch (device globals; no allocations allowed) ----------------
__device__ float g_lat[(size_t)T_SEQ * LATD];
__device__ float g_qbuf[(size_t)T_SEQ * QTOT];
__device__ float g_scores[(size_t)NHEAD * T_SEQ * T_SEQ];

__device__ bf16 g_xhi[(size_t)T_SEQ * NEMBD];
__device__ bf16 g_xlo[(size_t)T_SEQ * NEMBD];
__device__ bf16 g_wqkvThi[(size_t)NPAD1 * NEMBD];
__device__ bf16 g_wqkvTlo[(size_t)NPAD1 * NEMBD];
__device__ bf16 g_cqhi[(size_t)T_SEQ * QLOW];
__device__ bf16 g_cqlo[(size_t)T_SEQ * QLOW];
__device__ bf16 g_wqdecThi[(size_t)QTOT * QLOW];
__device__ bf16 g_wqdecTlo[(size_t)QTOT * QLOW];
__device__ bf16 g_qhi[(size_t)T_SEQ * QTOT];
__device__ bf16 g_qlo[(size_t)T_SEQ * QTOT];
__device__ bf16 g_khi[(size_t)T_SEQ * QKHS];
__device__ bf16 g_klo[(size_t)T_SEQ * QKHS];
__device__ bf16 g_vThi[(size_t)KVLOW * T_SEQ];
__device__ bf16 g_vTlo[(size_t)KVLOW * T_SEQ];
__device__ bf16 g_attnhi[(size_t)NHEAD * T_SEQ * T_SEQ];
__device__ bf16 g_attnlo[(size_t)NHEAD * T_SEQ * T_SEQ];
__device__ bf16 g_yhi[(size_t)T_SEQ * YTOT];
__device__ bf16 g_ylo[(size_t)T_SEQ * YTOT];
__device__ bf16 g_woutThi[(size_t)NEMBD * YTOT];
__device__ bf16 g_woutTlo[(size_t)NEMBD * YTOT];

// ---------------- helpers ----------------
__device__ __forceinline__ void hlsplit(float v, bf16& h, bf16& l) {
    h = __float2bfloat16(v);
    l = __float2bfloat16(v - __bfloat162float(h));
}
__device__ __forceinline__ uint32_t smem_u32(const void* p) {
    uint32_t a;
    asm("{ .reg .u64 t; cvta.to.shared.u64 t, %1; cvt.u32.u64 %0, t; }" : "=r"(a) : "l"(p));
    return a;
}

#define CPA(dst, src) \
    asm volatile("cp.async.cg.shared.global [%0], [%1], 16;\n" :: "r"(dst), "l"(src))
#define CP_COMMIT() asm volatile("cp.async.commit_group;\n" ::: "memory")
#define CP_WAIT(N)  asm volatile("cp.async.wait_group %0;\n" :: "n"(N) : "memory")

#define LDSM4(r, addr) \
    asm volatile("ldmatrix.sync.aligned.m8n8.x4.shared.b16 {%0,%1,%2,%3}, [%4];" \
        : "=r"((r)[0]), "=r"((r)[1]), "=r"((r)[2]), "=r"((r)[3]) : "r"(addr))

#define MMA(d, a, b) \
    asm volatile("mma.sync.aligned.m16n8k16.row.col.f32.bf16.bf16.f32 " \
        "{%0,%1,%2,%3}, {%4,%5,%6,%7}, {%8,%9}, {%0,%1,%2,%3};" \
        : "+f"((d)[0]), "+f"((d)[1]), "+f"((d)[2]), "+f"((d)[3]) \
        : "r"((a)[0]), "r"((a)[1]), "r"((a)[2]), "r"((a)[3]), "r"((b)[0]), "r"((b)[1]))

// ---------------- Conversion kernels ----------------
// f32 [R][C] (row stride ldin) -> hi/lo bf16 row-major [R][C]
__global__ void convpack_hl(const float* __restrict__ in, bf16* __restrict__ hi,
                            bf16* __restrict__ lo, int R, int C, int ldin)
{
    size_t idx = (size_t)blockIdx.x * 256 + threadIdx.x;
    int half = C >> 1;
    if (idx >= (size_t)R * half) return;
    int r = (int)(idx / half);
    int c = (int)(idx - (size_t)r * half) * 2;
    float v0 = in[(size_t)r * ldin + c];
    float v1 = in[(size_t)r * ldin + c + 1];
    bf16 h0, l0, h1, l1;
    hlsplit(v0, h0, l0); hlsplit(v1, h1, l1);
    *(__nv_bfloat162*)(hi + (size_t)r * C + c) = __nv_bfloat162(h0, h1);
    *(__nv_bfloat162*)(lo + (size_t)r * C + c) = __nv_bfloat162(l0, l1);
}

// f32 in [R][C] (row stride ldin) -> transposed hi/lo [Cout][R]; rows c>=C zero.
__global__ void convpackT_hl(const float* __restrict__ in, bf16* __restrict__ hi,
                             bf16* __restrict__ lo, int R, int C, int ldin)
{
    __shared__ float ts[32][33];
    const int tid = threadIdx.x;
    const int c0 = blockIdx.x * 32, r0 = blockIdx.y * 32;
    const int j = tid & 31;
    #pragma unroll
    for (int q = 0; q < 4; q++) {
        int i = (tid >> 5) + q * 8;
        ts[j][i] = (c0 + j < C) ? in[(size_t)(r0 + i) * ldin + (c0 + j)] : 0.f;
    }
    __syncthreads();
    const int cl = tid >> 3, g = tid & 7;
    bf16 h[4], l[4];
    #pragma unroll
    for (int q = 0; q < 4; q++) hlsplit(ts[cl][g * 4 + q], h[q], l[q]);
    size_t base = (size_t)(c0 + cl) * R + r0 + g * 4;
    *(__nv_bfloat162*)(hi + base)     = __nv_bfloat162(h[0], h[1]);
    *(__nv_bfloat162*)(hi + base + 2) = __nv_bfloat162(h[2], h[3]);
    *(__nv_bfloat162*)(lo + base)     = __nv_bfloat162(l[0], l[1]);
    *(__nv_bfloat162*)(lo + base + 2) = __nv_bfloat162(l[2], l[3]);
}

// ---------------- RoPE + hi/lo pack of q and k ----------------
__global__ void rope_pack_kernel(const float* __restrict__ lat, const float* __restrict__ qbuf,
                                 const float* __restrict__ cosT, const float* __restrict__ sinT,
                                 bf16* __restrict__ khi, bf16* __restrict__ klo,
                                 bf16* __restrict__ qhi, bf16* __restrict__ qlo)
{
    const int t = blockIdx.x, tid = threadIdx.x;
    __shared__ float cs[ROPEHS], sn[ROPEHS];
    if (tid < ROPEHS) {
        cs[tid] = cosT[(size_t)t * ROPEHS + tid];
        sn[tid] = sinT[(size_t)t * ROPEHS + tid];
    }
    __syncthreads();

    const float* lrow = lat + (size_t)t * LATD;
    bf16* krh = khi + (size_t)t * QKHS;
    bf16* krl = klo + (size_t)t * QKHS;
    for (int p = tid; p < QKHS / 2; p += 256) {
        int e = p * 2;
        float v[2];
        #pragma unroll
        for (int u = 0; u < 2; u++) {
            int ee = e + u;
            if (ee < KVLOW) v[u] = lrow[ee];
            else {
                int i2 = ee - KVLOW;
                float x = lrow[ee];
                v[u] = (i2 < 32) ? x * cs[i2] - lrow[ee + 32] * sn[i2]
                                 : x * cs[i2] + lrow[ee - 32] * sn[i2];
            }
        }
        bf16 h0, l0, h1, l1;
        hlsplit(v[0], h0, l0); hlsplit(v[1], h1, l1);
        *(__nv_bfloat162*)(krh + e) = __nv_bfloat162(h0, h1);
        *(__nv_bfloat162*)(krl + e) = __nv_bfloat162(l0, l1);
    }

    const float* qrow = qbuf + (size_t)t * QTOT;
    bf16* qrh = qhi + (size_t)t * QTOT;
    bf16* qrl = qlo + (size_t)t * QTOT;
    for (int p = tid; p < QTOT / 2; p += 256) {
        int e = p * 2;
        float v[2];
        #pragma unroll
        for (int u = 0; u < 2; u++) {
            int ee = e + u;
            int hh = ee / QKHS;
            int i = ee - hh * QKHS;
            if (i < KVLOW) v[u] = qrow[ee];
            else {
                int i2 = i - KVLOW;
                float x = qrow[ee];
                v[u] = (i2 < 32) ? x * cs[i2] - qrow[ee + 32] * sn[i2]
                                 : x * cs[i2] + qrow[ee - 32] * sn[i2];
            }
        }
        bf16 h0, l0, h1, l1;
        hlsplit(v[0], h0, l0); hlsplit(v[1], h1, l1);
        *(__nv_bfloat162*)(qrh + e) = __nv_bfloat162(h0, h1);
        *(__nv_bfloat162*)(qrl + e) = __nv_bfloat162(l0, l1);
    }
}

// ---------------- Softmax -> hi/lo attn ----------------
__global__ __launch_bounds__(256)
void softmax_kernel(const float* __restrict__ scores,
                    bf16* __restrict__ ahi, bf16* __restrict__ alo)
{
    __shared__ float srow[T_SEQ];
    __shared__ float red[8];
    const int t = blockIdx.x, h = blockIdx.y, tid = threadIdx.x;
    const float* row = scores + ((size_t)h * T_SEQ + t) * T_SEQ;
    const int n = t + 1;

    float m = -3.4e38f;
    for (int s = tid; s < n; s += 256) { float v = row[s]; srow[s] = v; m = fmaxf(m, v); }
    #pragma unroll
    for (int o = 16; o; o >>= 1) m = fmaxf(m, __shfl_xor_sync(0xffffffffu, m, o));
    if ((tid & 31) == 0) red[tid >> 5] = m;
    __syncthreads();
    float mmax = red[0];
    #pragma unroll
    for (int i = 1; i < 8; i++) mmax = fmaxf(mmax, red[i]);
    __syncthreads();

    float sum = 0.f;
    for (int s = tid; s < n; s += 256) { float e = __expf(srow[s] - mmax); srow[s] = e; sum += e; }
    #pragma unroll
    for (int o = 16; o; o >>= 1) sum += __shfl_xor_sync(0xffffffffu, sum, o);
    if ((tid & 31) == 0) red[tid >> 5] = sum;
    __syncthreads();
    float total = 0.f;
    #pragma unroll
    for (int i = 0; i < 8; i++) total += red[i];
    const float inv = 1.f / total;

    bf16* rh = ahi + ((size_t)h * T_SEQ + t) * T_SEQ;
    bf16* rl = alo + ((size_t)h * T_SEQ + t) * T_SEQ;
    const int kpad = ((t >> 7) + 1) << 7;
    for (int p = tid; p < (kpad >> 1); p += 256) {
        int s0 = 2 * p;
        float v0 = (s0 <= t) ? srow[s0] * inv : 0.f;
        float v1 = (s0 + 1 <= t) ? srow[s0 + 1] * inv : 0.f;
        bf16 h0, l0, h1, l1;
        hlsplit(v0, h0, l0); hlsplit(v1, h1, l1);
        *(__nv_bfloat162*)(rh + s0) = __nv_bfloat162(h0, h1);
        *(__nv_bfloat162*)(rl + s0) = __nv_bfloat162(l0, l1);
    }
}

// ---------------- mma.sync GEMM: C = alpha * A * B^T ----------------
// A[M][K], B[N][K] hi/lo bf16, both K-contiguous. 128x128 CTA tile, BK=32,
// 8 warps (2m x 4n; 64x32 warp tile), cp.async double buffer.
#define ROWB   80                 // 64B data + 16B pad per 32-half row
#define TILEB  (128 * ROWB)       // 10240
#define STAGEB (4 * TILEB)        // 40960: Ahi, Alo, Bhi, Blo
#define SMEM_TOT (2 * STAGEB)     // 81920

template<bool CSKIP, bool CK, int EPI>   // EPI: 0 -> f32 C, 1 -> hi/lo bf16 C
__global__ __launch_bounds__(256, 1)
void mmagemm(const bf16* __restrict__ Ahi, const bf16* __restrict__ Alo,
             const bf16* __restrict__ Bhi, const bf16* __restrict__ Blo,
             float* __restrict__ Cf, bf16* __restrict__ Chi, bf16* __restrict__ Clo,
             int M, int N, int K, int ldA, int ldB, int ldC,
             long sA, long sB, long sC, float alpha)
{
    extern __shared__ char smc[];
    const int bx = blockIdx.x, by = blockIdx.y, z = blockIdx.z;
    if (CSKIP && bx > by) return;

    Ahi += (size_t)z * sA;  Alo += (size_t)z * sA;
    Bhi += (size_t)z * sB;  Blo += (size_t)z * sB;

    const int Keff = CK ? min(K, (by + 1) * 128) : K;
    const int nc = Keff >> 5;
    const int tid = threadIdx.x, wid = tid >> 5, lane = tid & 31;
    const int m0 = by * 128, n0 = bx * 128;
    const uint32_t smb = smem_u32(smc);

    // ---- load mapping: thread -> row tid>>1, two 16B chunks at (tid&1)*32 ----
    const int lrow = tid >> 1;
    const int lcb  = (tid & 1) * 32;   // byte offset within 64B row
    const bf16* gAh = Ahi + (size_t)(m0 + lrow) * ldA + (lcb >> 1);
    const bf16* gAl = Alo + (size_t)(m0 + lrow) * ldA + (lcb >> 1);
    const bf16* gBh = Bhi + (size_t)(n0 + lrow) * ldB + (lcb >> 1);
    const bf16* gBl = Blo + (size_t)(n0 + lrow) * ldB + (lcb >> 1);
    const uint32_t sd = smb + lrow * ROWB + lcb;

#define PREFETCH(c, s) do { \
        uint32_t d_ = sd + (s) * STAGEB; \
        const bf16* p_ = gAh + (size_t)(c) * 32; \
        CPA(d_, p_); CPA(d_ + 16, p_ + 8); \
        p_ = gAl + (size_t)(c) * 32; \
        CPA(d_ + TILEB, p_); CPA(d_ + TILEB + 16, p_ + 8); \
        p_ = gBh + (size_t)(c) * 32; \
        CPA(d_ + 2 * TILEB, p_); CPA(d_ + 2 * TILEB + 16, p_ + 8); \
        p_ = gBl + (size_t)(c) * 32; \
        CPA(d_ + 3 * TILEB, p_); CPA(d_ + 3 * TILEB + 16, p_ + 8); \
        CP_COMMIT(); \
    } while (0)

    // ---- compute mapping ----
    const int wm = (wid & 1) * 64;   // warp m offset in tile
    const int wn = (wid >> 1) * 32;  // warp n offset in tile
    // A ldmatrix: row = wm + mi*16 + (lane&15), col halves = kk + (lane>>4)*8
    const uint32_t aOff = (uint32_t)((wm + (lane & 15)) * ROWB + ((lane >> 4) << 4));
    // B ldmatrix: row = wn + nb*16 + (lane&7) + ((lane&16)>>1), col halves = kk + (lane&8)
    const uint32_t bOff = (uint32_t)((wn + (lane & 7) + ((lane & 16) >> 1)) * ROWB + ((lane & 8) << 1));

    float acc[4][4][4];
    #pragma unroll
    for (int i = 0; i < 4; i++)
        #pragma unroll
        for (int j = 0; j < 4; j++)
            #pragma unroll
            for (int q = 0; q < 4; q++) acc[i][j][q] = 0.f;

    PREFETCH(0, 0);

    for (int c = 0; c < nc; ++c) {
        const int buf = c & 1;
        if (c + 1 < nc) { PREFETCH(c + 1, (c + 1) & 1); CP_WAIT(1); }
        else            { CP_WAIT(0); }
        __syncthreads();

        const uint32_t base = smb + buf * STAGEB;
        #pragma unroll
        for (int half = 0; half < 2; half++) {
            const uint32_t kkb = half * 32;   // 16 halves = 32B
            uint32_t ah[4][4], al[4][4];
            #pragma unroll
            for (int mi = 0; mi < 4; mi++) {
                LDSM4(ah[mi], base + aOff + mi * 16 * ROWB + kkb);
                LDSM4(al[mi], base + TILEB + aOff + mi * 16 * ROWB + kkb);
            }
            uint32_t bh[4][2], bl[4][2];
            #pragma unroll
            for (int nb = 0; nb < 2; nb++) {
                uint32_t r4[4];
                LDSM4(r4, base + 2 * TILEB + bOff + nb * 16 * ROWB + kkb);
                bh[nb * 2][0] = r4[0]; bh[nb * 2][1] = r4[1];
                bh[nb * 2 + 1][0] = r4[2]; bh[nb * 2 + 1][1] = r4[3];
                LDSM4(r4, base + 3 * TILEB + bOff + nb * 16 * ROWB + kkb);
                bl[nb * 2][0] = r4[0]; bl[nb * 2][1] = r4[1];
                bl[nb * 2 + 1][0] = r4[2]; bl[nb * 2 + 1][1] = r4[3];
            }
            #pragma unroll
            for (int mi = 0; mi < 4; mi++)
                #pragma unroll
                for (int ni = 0; ni < 4; ni++) {
                    MMA(acc[mi][ni], ah[mi], bh[ni]);
                    MMA(acc[mi][ni], ah[mi], bl[ni]);
                    MMA(acc[mi][ni], al[mi], bh[ni]);
                }
        }
        __syncthreads();
    }
#undef PREFETCH

    // ---- epilogue ----
    const int er = lane >> 2, ec = (lane & 3) * 2;
    if (EPI == 0) {
        float* Cz = Cf + (size_t)z * sC;
        #pragma unroll
        for (int mi = 0; mi < 4; mi++) {
            const int r1 = m0 + wm + mi * 16 + er;
            #pragma unroll
            for (int ni = 0; ni < 4; ni++) {
                const int c1 = n0 + wn + ni * 8 + ec;
                if (c1 < N) {
                    float2 v0 = make_float2(acc[mi][ni][0] * alpha, acc[mi][ni][1] * alpha);
                    float2 v1 = make_float2(acc[mi][ni][2] * alpha, acc[mi][ni][3] * alpha);
                    *(float2*)(Cz + (size_t)r1 * ldC + c1) = v0;
                    *(float2*)(Cz + (size_t)(r1 + 8) * ldC + c1) = v1;
                }
            }
        }
    } else {
        bf16* Ch = Chi + (size_t)z * sC;
        bf16* Cl = Clo + (size_t)z * sC;
        #pragma unroll
        for (int mi = 0; mi < 4; mi++) {
            const int r1 = m0 + wm + mi * 16 + er;
            #pragma unroll
            for (int ni = 0; ni < 4; ni++) {
                const int c1 = n0 + wn + ni * 8 + ec;
                if (c1 < N) {
                    bf16 h0, l0, h1, l1;
                    hlsplit(acc[mi][ni][0] * alpha, h0, l0);
                    hlsplit(acc[mi][ni][1] * alpha, h1, l1);
                    *(__nv_bfloat162*)(Ch + (size_t)r1 * ldC + c1) = __nv_bfloat162(h0, h1);
                    *(__nv_bfloat162*)(Cl + (size_t)r1 * ldC + c1) = __nv_bfloat162(l0, l1);
                    hlsplit(acc[mi][ni][2] * alpha, h0, l0);
                    hlsplit(acc[mi][ni][3] * alpha, h1, l1);
                    *(__nv_bfloat162*)(Ch + (size_t)(r1 + 8) * ldC + c1) = __nv_bfloat162(h0, h1);
                    *(__nv_bfloat162*)(Cl + (size_t)(r1 + 8) * ldC + c1) = __nv_bfloat162(l0, l1);
                }
            }
        }
    }
}

// ---------------- Launch ----------------
extern "C" void kernel_launch(void* const* d_in, const int* in_sizes, int n_in,
                              void* d_out, int out_size)
{
    (void)in_sizes; (void)n_in; (void)out_size;
    const float* x     = (const float*)d_in[0];
    const float* cosT  = (const float*)d_in[1];
    const float* sinT  = (const float*)d_in[2];
    const float* Wqkv  = (const float*)d_in[3];
    const float* Wqdec = (const float*)d_in[4];
    const float* Wout  = (const float*)d_in[5];
    float* out = (float*)d_out;

    float *lat, *qbuf, *scores;
    bf16 *xhi, *xlo, *wqkvThi, *wqkvTlo, *cqhi, *cqlo, *wqdecThi, *wqdecTlo;
    bf16 *qhi, *qlo, *khi, *klo, *vThi, *vTlo, *attnhi, *attnlo, *yhi, *ylo, *woutThi, *woutTlo;
    cudaGetSymbolAddress((void**)&lat, g_lat);
    cudaGetSymbolAddress((void**)&qbuf, g_qbuf);
    cudaGetSymbolAddress((void**)&scores, g_scores);
    cudaGetSymbolAddress((void**)&xhi, g_xhi);       cudaGetSymbolAddress((void**)&xlo, g_xlo);
    cudaGetSymbolAddress((void**)&wqkvThi, g_wqkvThi); cudaGetSymbolAddress((void**)&wqkvTlo, g_wqkvTlo);
    cudaGetSymbolAddress((void**)&cqhi, g_cqhi);     cudaGetSymbolAddress((void**)&cqlo, g_cqlo);
    cudaGetSymbolAddress((void**)&wqdecThi, g_wqdecThi); cudaGetSymbolAddress((void**)&wqdecTlo, g_wqdecTlo);
    cudaGetSymbolAddress((void**)&qhi, g_qhi);       cudaGetSymbolAddress((void**)&qlo, g_qlo);
    cudaGetSymbolAddress((void**)&khi, g_khi);       cudaGetSymbolAddress((void**)&klo, g_klo);
    cudaGetSymbolAddress((void**)&vThi, g_vThi);     cudaGetSymbolAddress((void**)&vTlo, g_vTlo);
    cudaGetSymbolAddress((void**)&attnhi, g_attnhi); cudaGetSymbolAddress((void**)&attnlo, g_attnlo);
    cudaGetSymbolAddress((void**)&yhi, g_yhi);       cudaGetSymbolAddress((void**)&ylo, g_ylo);
    cudaGetSymbolAddress((void**)&woutThi, g_woutThi); cudaGetSymbolAddress((void**)&woutTlo, g_woutTlo);

    cudaFuncSetAttribute((const void*)mmagemm<false, false, 0>,
                         cudaFuncAttributeMaxDynamicSharedMemorySize, SMEM_TOT);
    cudaFuncSetAttribute((const void*)mmagemm<true, false, 0>,
                         cudaFuncAttributeMaxDynamicSharedMemorySize, SMEM_TOT);
    cudaFuncSetAttribute((const void*)mmagemm<false, true, 1>,
                         cudaFuncAttributeMaxDynamicSharedMemorySize, SMEM_TOT);

    const float scale = 0.04419417382415922f;   // 1/sqrt(512)
    const dim3 blk(256);

    // ---- conversions of inputs ----
    convpack_hl<<<(T_SEQ * NEMBD / 2 + 255) / 256, blk>>>(x, xhi, xlo, T_SEQ, NEMBD, NEMBD);
    convpackT_hl<<<dim3(NPAD1 / 32, NEMBD / 32), blk>>>(Wqkv, wqkvThi, wqkvTlo, NEMBD, LATD, LATD);
    convpackT_hl<<<dim3(QTOT / 32, QLOW / 32), blk>>>(Wqdec, wqdecThi, wqdecTlo, QLOW, QTOT, QTOT);
    convpackT_hl<<<dim3(NEMBD / 32, YTOT / 32), blk>>>(Wout, woutThi, woutTlo, YTOT, NEMBD, NEMBD);

    // ---- G1: lat = x @ Wqkv  [2048 x 1600] (N padded to 1664 in B) ----
    mmagemm<false, false, 0><<<dim3(13, 16, 1), blk, SMEM_TOT>>>(
        xhi, xlo, wqkvThi, wqkvTlo, lat, nullptr, nullptr,
        T_SEQ, LATD, NEMBD, NEMBD, NEMBD, LATD, 0, 0, 0, 1.f);

    // ---- conversions from lat ----
    convpack_hl<<<(T_SEQ * QLOW / 2 + 255) / 256, blk>>>(lat + (KVLOW + ROPEHS), cqhi, cqlo,
                                                         T_SEQ, QLOW, LATD);
    convpackT_hl<<<dim3(KVLOW / 32, T_SEQ / 32), blk>>>(lat, vThi, vTlo, T_SEQ, KVLOW, LATD);

    // ---- G2: qbuf = c_q @ Wqdec  [2048 x 9216] ----
    mmagemm<false, false, 0><<<dim3(72, 16, 1), blk, SMEM_TOT>>>(
        cqhi, cqlo, wqdecThi, wqdecTlo, qbuf, nullptr, nullptr,
        T_SEQ, QTOT, QLOW, QLOW, QLOW, QTOT, 0, 0, 0, 1.f);

    // ---- RoPE + hi/lo q/k ----
    rope_pack_kernel<<<T_SEQ, blk>>>(lat, qbuf, cosT, sinT, khi, klo, qhi, qlo);

    // ---- scores[h] = scale * q_h @ k^T, causal tile skip ----
    mmagemm<true, false, 0><<<dim3(16, 16, NHEAD), blk, SMEM_TOT>>>(
        qhi, qlo, khi, klo, scores, nullptr, nullptr,
        T_SEQ, T_SEQ, QKHS, QTOT, QKHS, T_SEQ,
        (long)QKHS, 0, (long)T_SEQ * T_SEQ, scale);

    // ---- softmax -> hi/lo attn ----
    softmax_kernel<<<dim3(T_SEQ, NHEAD), blk>>>(scores, attnhi, attnlo);

    // ---- PV: y_h = attn_h @ v (K causal-truncated), bf16 hi/lo epilogue ----
    mmagemm<false, true, 1><<<dim3(4, 16, NHEAD), blk, SMEM_TOT>>>(
        attnhi, attnlo, vThi, vTlo, nullptr, yhi, ylo,
        T_SEQ, KVLOW, T_SEQ, T_SEQ, T_SEQ, YTOT,
        (long)T_SEQ * T_SEQ, 0, (long)KVLOW, 1.f);

    // ---- G3: out = y @ Wout  [2048 x 2048] ----
    mmagemm<false, false, 0><<<dim3(16, 16, 1), blk, SMEM_TOT>>>(
        yhi, ylo, woutThi, woutTlo, out, nullptr, nullptr,
        T_SEQ, NEMBD, YTOT, YTOT, YTOT, NEMBD, 0, 0, 0, 1.f);
}

// round 4
// speedup vs baseline: 3.1637x; 1.0869x over previous
#include <cuda_runtime.h>
#include <cuda_bf16.h>
#include <cstdint>

// ---------------- Problem constants ----------------
#define T_SEQ   2048
#define NEMBD   2048
#define NHEAD   16
#define KVLOW   512
#define QLOW    1024
#define ROPEHS  64
#define QKHS    576
#define LATD    1600
#define QTOT    9216
#define YTOT    8192
#define NPAD1   1664   // 1600 padded up to 13*128

typedef __nv_bfloat16 bf16;

// ---------------- Scratch (device globals; no allocations allowed) ----------------
__device__ float g_lat[(size_t)T_SEQ * LATD];
__device__ float g_qbuf[(size_t)T_SEQ * QTOT];
__device__ float g_scores[(size_t)NHEAD * T_SEQ * T_SEQ];

__device__ bf16 g_xhi[(size_t)T_SEQ * NEMBD];
__device__ bf16 g_xlo[(size_t)T_SEQ * NEMBD];
__device__ bf16 g_wqkvThi[(size_t)NPAD1 * NEMBD];
__device__ bf16 g_wqkvTlo[(size_t)NPAD1 * NEMBD];
__device__ bf16 g_cqhi[(size_t)T_SEQ * QLOW];
__device__ bf16 g_cqlo[(size_t)T_SEQ * QLOW];
__device__ bf16 g_wqdecThi[(size_t)QTOT * QLOW];
__device__ bf16 g_wqdecTlo[(size_t)QTOT * QLOW];
__device__ bf16 g_qhi[(size_t)T_SEQ * QTOT];
__device__ bf16 g_qlo[(size_t)T_SEQ * QTOT];
__device__ bf16 g_khi[(size_t)T_SEQ * QKHS];
__device__ bf16 g_klo[(size_t)T_SEQ * QKHS];
__device__ bf16 g_vThi[(size_t)KVLOW * T_SEQ];
__device__ bf16 g_vTlo[(size_t)KVLOW * T_SEQ];
__device__ bf16 g_attnhi[(size_t)NHEAD * T_SEQ * T_SEQ];
__device__ bf16 g_attnlo[(size_t)NHEAD * T_SEQ * T_SEQ];
__device__ bf16 g_yhi[(size_t)T_SEQ * YTOT];
__device__ bf16 g_ylo[(size_t)T_SEQ * YTOT];
__device__ bf16 g_woutThi[(size_t)NEMBD * YTOT];
__device__ bf16 g_woutTlo[(size_t)NEMBD * YTOT];

// ---------------- helpers ----------------
__device__ __forceinline__ void hlsplit(float v, bf16& h, bf16& l) {
    h = __float2bfloat16(v);
    l = __float2bfloat16(v - __bfloat162float(h));
}
__device__ __forceinline__ uint32_t smem_u32(const void* p) {
    uint32_t a;
    asm("{ .reg .u64 t; cvta.to.shared.u64 t, %1; cvt.u32.u64 %0, t; }" : "=r"(a) : "l"(p));
    return a;
}

#define CPA(dst, src) \
    asm volatile("cp.async.cg.shared.global [%0], [%1], 16;\n" :: "r"(dst), "l"(src))
#define CP_COMMIT() asm volatile("cp.async.commit_group;\n" ::: "memory")
#define CP_WAIT(N)  asm volatile("cp.async.wait_group %0;\n" :: "n"(N) : "memory")

#define LDSM4(r, addr) \
    asm volatile("ldmatrix.sync.aligned.m8n8.x4.shared.b16 {%0,%1,%2,%3}, [%4];" \
        : "=r"((r)[0]), "=r"((r)[1]), "=r"((r)[2]), "=r"((r)[3]) : "r"(addr))

#define MMA(d, a, b) \
    asm volatile("mma.sync.aligned.m16n8k16.row.col.f32.bf16.bf16.f32 " \
        "{%0,%1,%2,%3}, {%4,%5,%6,%7}, {%8,%9}, {%0,%1,%2,%3};" \
        : "+f"((d)[0]), "+f"((d)[1]), "+f"((d)[2]), "+f"((d)[3]) \
        : "r"((a)[0]), "r"((a)[1]), "r"((a)[2]), "r"((a)[3]), "r"((b)[0]), "r"((b)[1]))

// ---------------- Conversion bodies ----------------
__device__ __forceinline__ void convpack_body(const float* __restrict__ in,
                                              bf16* __restrict__ hi, bf16* __restrict__ lo,
                                              int R, int C, int ldin, size_t idx)
{
    int half = C >> 1;
    if (idx >= (size_t)R * half) return;
    int r = (int)(idx / half);
    int c = (int)(idx - (size_t)r * half) * 2;
    float v0 = in[(size_t)r * ldin + c];
    float v1 = in[(size_t)r * ldin + c + 1];
    bf16 h0, l0, h1, l1;
    hlsplit(v0, h0, l0); hlsplit(v1, h1, l1);
    *(__nv_bfloat162*)(hi + (size_t)r * C + c) = __nv_bfloat162(h0, h1);
    *(__nv_bfloat162*)(lo + (size_t)r * C + c) = __nv_bfloat162(l0, l1);
}

__device__ __forceinline__ void cvT_body(const float* __restrict__ in,
                                         bf16* __restrict__ hi, bf16* __restrict__ lo,
                                         int R, int C, int ldin, int bx, int by,
                                         int tid, float (*ts)[33])
{
    const int c0 = bx * 32, r0 = by * 32;
    const int j = tid & 31;
    #pragma unroll
    for (int q = 0; q < 4; q++) {
        int i = (tid >> 5) + q * 8;
        ts[j][i] = (c0 + j < C) ? in[(size_t)(r0 + i) * ldin + (c0 + j)] : 0.f;
    }
    __syncthreads();
    const int cl = tid >> 3, g = tid & 7;
    bf16 h[4], l[4];
    #pragma unroll
    for (int q = 0; q < 4; q++) hlsplit(ts[cl][g * 4 + q], h[q], l[q]);
    size_t base = (size_t)(c0 + cl) * R + r0 + g * 4;
    *(__nv_bfloat162*)(hi + base)     = __nv_bfloat162(h[0], h[1]);
    *(__nv_bfloat162*)(hi + base + 2) = __nv_bfloat162(h[2], h[3]);
    *(__nv_bfloat162*)(lo + base)     = __nv_bfloat162(l[0], l[1]);
    *(__nv_bfloat162*)(lo + base + 2) = __nv_bfloat162(l[2], l[3]);
}

// launch 0: x -> hi/lo
__global__ void conv_x(const float* __restrict__ x, bf16* __restrict__ hi, bf16* __restrict__ lo)
{
    convpack_body(x, hi, lo, T_SEQ, NEMBD, NEMBD, (size_t)blockIdx.x * 256 + threadIdx.x);
}
// launch 1: WqkvT
__global__ void conv_wqkv(const float* __restrict__ w, bf16* __restrict__ hi, bf16* __restrict__ lo)
{
    __shared__ float ts[32][33];
    cvT_body(w, hi, lo, NEMBD, LATD, LATD, blockIdx.x, blockIdx.y, threadIdx.x, ts);
}
// launch 2: fused WqdecT + WoutT
#define NQDBLK ((QTOT / 32) * (QLOW / 32))      // 9216
#define NWOBLK ((NEMBD / 32) * (YTOT / 32))     // 16384
__global__ void conv_w2(const float* __restrict__ wqdec, bf16* __restrict__ qdhi, bf16* __restrict__ qdlo,
                        const float* __restrict__ wout, bf16* __restrict__ wohi, bf16* __restrict__ wolo)
{
    __shared__ float ts[32][33];
    int b = blockIdx.x;
    if (b < NQDBLK) {
        cvT_body(wqdec, qdhi, qdlo, QLOW, QTOT, QTOT, b % (QTOT / 32), b / (QTOT / 32), threadIdx.x, ts);
    } else {
        b -= NQDBLK;
        cvT_body(wout, wohi, wolo, YTOT, NEMBD, NEMBD, b % (NEMBD / 32), b / (NEMBD / 32), threadIdx.x, ts);
    }
}
// launch 4: fused cq convpack + vT transpose (both read lat)
#define NCQBLK 4096                              // 2048*1024/2/256
#define NVTBLK ((KVLOW / 32) * (T_SEQ / 32))     // 1024
__global__ void conv_lat(const float* __restrict__ lat,
                         bf16* __restrict__ cqhi, bf16* __restrict__ cqlo,
                         bf16* __restrict__ vthi, bf16* __restrict__ vtlo)
{
    __shared__ float ts[32][33];
    int b = blockIdx.x;
    if (b < NCQBLK) {
        convpack_body(lat + (KVLOW + ROPEHS), cqhi, cqlo, T_SEQ, QLOW, LATD,
                      (size_t)b * 256 + threadIdx.x);
    } else {
        b -= NCQBLK;
        cvT_body(lat, vthi, vtlo, T_SEQ, KVLOW, LATD, b % (KVLOW / 32), b / (KVLOW / 32),
                 threadIdx.x, ts);
    }
}

// ---------------- RoPE + hi/lo pack of q and k ----------------
__global__ void rope_pack_kernel(const float* __restrict__ lat, const float* __restrict__ qbuf,
                                 const float* __restrict__ cosT, const float* __restrict__ sinT,
                                 bf16* __restrict__ khi, bf16* __restrict__ klo,
                                 bf16* __restrict__ qhi, bf16* __restrict__ qlo)
{
    const int t = blockIdx.x, tid = threadIdx.x;
    __shared__ float cs[ROPEHS], sn[ROPEHS];
    if (tid < ROPEHS) {
        cs[tid] = cosT[(size_t)t * ROPEHS + tid];
        sn[tid] = sinT[(size_t)t * ROPEHS + tid];
    }
    __syncthreads();

    const float* lrow = lat + (size_t)t * LATD;
    bf16* krh = khi + (size_t)t * QKHS;
    bf16* krl = klo + (size_t)t * QKHS;
    for (int p = tid; p < QKHS / 2; p += 256) {
        int e = p * 2;
        float v[2];
        #pragma unroll
        for (int u = 0; u < 2; u++) {
            int ee = e + u;
            if (ee < KVLOW) v[u] = lrow[ee];
            else {
                int i2 = ee - KVLOW;
                float xv = lrow[ee];
                v[u] = (i2 < 32) ? xv * cs[i2] - lrow[ee + 32] * sn[i2]
                                 : xv * cs[i2] + lrow[ee - 32] * sn[i2];
            }
        }
        bf16 h0, l0, h1, l1;
        hlsplit(v[0], h0, l0); hlsplit(v[1], h1, l1);
        *(__nv_bfloat162*)(krh + e) = __nv_bfloat162(h0, h1);
        *(__nv_bfloat162*)(krl + e) = __nv_bfloat162(l0, l1);
    }

    const float* qrow = qbuf + (size_t)t * QTOT;
    bf16* qrh = qhi + (size_t)t * QTOT;
    bf16* qrl = qlo + (size_t)t * QTOT;
    for (int p = tid; p < QTOT / 2; p += 256) {
        int e = p * 2;
        float v[2];
        #pragma unroll
        for (int u = 0; u < 2; u++) {
            int ee = e + u;
            int hh = ee / QKHS;
            int i = ee - hh * QKHS;
            if (i < KVLOW) v[u] = qrow[ee];
            else {
                int i2 = i - KVLOW;
                float xv = qrow[ee];
                v[u] = (i2 < 32) ? xv * cs[i2] - qrow[ee + 32] * sn[i2]
                                 : xv * cs[i2] + qrow[ee - 32] * sn[i2];
            }
        }
        bf16 h0, l0, h1, l1;
        hlsplit(v[0], h0, l0); hlsplit(v[1], h1, l1);
        *(__nv_bfloat162*)(qrh + e) = __nv_bfloat162(h0, h1);
        *(__nv_bfloat162*)(qrl + e) = __nv_bfloat162(l0, l1);
    }
}

// ---------------- Softmax -> hi/lo attn (zero-filled to 256-boundary) ----------------
__global__ __launch_bounds__(256)
void softmax_kernel(const float* __restrict__ scores,
                    bf16* __restrict__ ahi, bf16* __restrict__ alo)
{
    __shared__ float srow[T_SEQ];
    __shared__ float red[8];
    const int t = blockIdx.x, h = blockIdx.y, tid = threadIdx.x;
    const float* row = scores + ((size_t)h * T_SEQ + t) * T_SEQ;
    const int n = t + 1;

    float m = -3.4e38f;
    for (int s = tid; s < n; s += 256) { float v = row[s]; srow[s] = v; m = fmaxf(m, v); }
    #pragma unroll
    for (int o = 16; o; o >>= 1) m = fmaxf(m, __shfl_xor_sync(0xffffffffu, m, o));
    if ((tid & 31) == 0) red[tid >> 5] = m;
    __syncthreads();
    float mmax = red[0];
    #pragma unroll
    for (int i = 1; i < 8; i++) mmax = fmaxf(mmax, red[i]);
    __syncthreads();

    float sum = 0.f;
    for (int s = tid; s < n; s += 256) { float e = __expf(srow[s] - mmax); srow[s] = e; sum += e; }
    #pragma unroll
    for (int o = 16; o; o >>= 1) sum += __shfl_xor_sync(0xffffffffu, sum, o);
    if ((tid & 31) == 0) red[tid >> 5] = sum;
    __syncthreads();
    float total = 0.f;
    #pragma unroll
    for (int i = 0; i < 8; i++) total += red[i];
    const float inv = 1.f / total;

    bf16* rh = ahi + ((size_t)h * T_SEQ + t) * T_SEQ;
    bf16* rl = alo + ((size_t)h * T_SEQ + t) * T_SEQ;
    const int kpad = ((t >> 8) + 1) << 8;   // 256-granular for PV K truncation
    for (int p = tid; p < (kpad >> 1); p += 256) {
        int s0 = 2 * p;
        float v0 = (s0 <= t) ? srow[s0] * inv : 0.f;
        float v1 = (s0 + 1 <= t) ? srow[s0 + 1] * inv : 0.f;
        bf16 h0, l0, h1, l1;
        hlsplit(v0, h0, l0); hlsplit(v1, h1, l1);
        *(__nv_bfloat162*)(rh + s0) = __nv_bfloat162(h0, h1);
        *(__nv_bfloat162*)(rl + s0) = __nv_bfloat162(l0, l1);
    }
}

// ---------------- mma.sync GEMM: C = alpha * A * B^T ----------------
// CTA tile 256x128, 512 threads (16 warps, 4m x 4n of 64x32), BK=32,
// 3-stage cp.async pipeline. A[M][K], B[N][K] hi/lo bf16, K-contiguous.
#define ROWB   80                  // 64B data + 16B pad
#define ATILE  (256 * ROWB)        // 20480
#define BTILE  (128 * ROWB)        // 10240
#define STAGEB (2 * ATILE + 2 * BTILE)  // 61440: Ahi, Alo, Bhi, Blo
#define NSTAGE 3
#define SMEM_TOT (NSTAGE * STAGEB) // 184320

template<int CSKIP, bool CK, int EPI>   // EPI: 0 -> f32 C, 1 -> hi/lo bf16 C
__global__ __launch_bounds__(512)
void mmagemm(const bf16* __restrict__ Ahi, const bf16* __restrict__ Alo,
             const bf16* __restrict__ Bhi, const bf16* __restrict__ Blo,
             float* __restrict__ Cf, bf16* __restrict__ Chi, bf16* __restrict__ Clo,
             int M, int N, int K, int ldA, int ldB, int ldC,
             long sA, long sB, long sC, float alpha)
{
    extern __shared__ char smc[];
    const int bx = blockIdx.x, by = blockIdx.y, z = blockIdx.z;
    if (CSKIP && bx > 2 * by + 1) return;   // tile fully above causal diagonal

    Ahi += (size_t)z * sA;  Alo += (size_t)z * sA;
    Bhi += (size_t)z * sB;  Blo += (size_t)z * sB;

    const int Keff = CK ? min(K, (by + 1) * 256) : K;
    const int nc = Keff >> 5;
    const int tid = threadIdx.x, wid = tid >> 5, lane = tid & 31;
    const int m0 = by * 256, n0 = bx * 128;
    const uint32_t smb = smem_u32(smc);

    // ---- load mapping ----
    const int arow = tid >> 1, aseg = (tid & 1) * 32;   // A: 256 rows x 2 segs of 32B
    const int brow = tid >> 2, bseg = (tid & 3) * 16;   // B: 128 rows x 4 segs of 16B
    const bf16* gAh = Ahi + (size_t)(m0 + arow) * ldA + (aseg >> 1);
    const bf16* gAl = Alo + (size_t)(m0 + arow) * ldA + (aseg >> 1);
    const bf16* gBh = Bhi + (size_t)(n0 + brow) * ldB + (bseg >> 1);
    const bf16* gBl = Blo + (size_t)(n0 + brow) * ldB + (bseg >> 1);
    const uint32_t aDst = (uint32_t)(arow * ROWB + aseg);
    const uint32_t bDst = (uint32_t)(brow * ROWB + bseg);

#define PREFETCH(c, s) do { \
        uint32_t b_ = smb + (uint32_t)(s) * STAGEB; \
        const bf16* p_ = gAh + (size_t)(c) * 32; \
        CPA(b_ + aDst, p_); CPA(b_ + aDst + 16, p_ + 8); \
        p_ = gAl + (size_t)(c) * 32; \
        CPA(b_ + ATILE + aDst, p_); CPA(b_ + ATILE + aDst + 16, p_ + 8); \
        p_ = gBh + (size_t)(c) * 32; \
        CPA(b_ + 2 * ATILE + bDst, p_); \
        p_ = gBl + (size_t)(c) * 32; \
        CPA(b_ + 2 * ATILE + BTILE + bDst, p_); \
        CP_COMMIT(); \
    } while (0)

    // ---- compute mapping: warp tile 64x32 ----
    const int wm = (wid & 3) * 64;
    const int wn = (wid >> 2) * 32;
    const uint32_t aOff = (uint32_t)((wm + (lane & 15)) * ROWB + ((lane >> 4) << 4));
    const uint32_t bOff = (uint32_t)((wn + (lane & 7) + ((lane & 16) >> 1)) * ROWB + ((lane & 8) << 1));

    float acc[4][4][4];
    #pragma unroll
    for (int i = 0; i < 4; i++)
        #pragma unroll
        for (int j = 0; j < 4; j++)
            #pragma unroll
            for (int q = 0; q < 4; q++) acc[i][j][q] = 0.f;

    PREFETCH(0, 0);
    PREFETCH(1, 1);

    int st = 0;       // stage of chunk c
    for (int c = 0; c < nc; ++c) {
        if (c + 2 < nc) {
            int ps = st + 2; if (ps >= NSTAGE) ps -= NSTAGE;
            PREFETCH(c + 2, ps);
            CP_WAIT(2);
        } else if (c + 1 < nc) {
            CP_WAIT(1);
        } else {
            CP_WAIT(0);
        }
        __syncthreads();

        const uint32_t base = smb + (uint32_t)st * STAGEB;
        #pragma unroll
        for (int half = 0; half < 2; half++) {
            const uint32_t kkb = half * 32;
            uint32_t ah[4][4], al[4][4];
            #pragma unroll
            for (int mi = 0; mi < 4; mi++) {
                LDSM4(ah[mi], base + aOff + mi * 16 * ROWB + kkb);
                LDSM4(al[mi], base + ATILE + aOff + mi * 16 * ROWB + kkb);
            }
            uint32_t bh[4][2], bl[4][2];
            #pragma unroll
            for (int nb = 0; nb < 2; nb++) {
                uint32_t r4[4];
                LDSM4(r4, base + 2 * ATILE + bOff + nb * 16 * ROWB + kkb);
                bh[nb * 2][0] = r4[0]; bh[nb * 2][1] = r4[1];
                bh[nb * 2 + 1][0] = r4[2]; bh[nb * 2 + 1][1] = r4[3];
                LDSM4(r4, base + 2 * ATILE + BTILE + bOff + nb * 16 * ROWB + kkb);
                bl[nb * 2][0] = r4[0]; bl[nb * 2][1] = r4[1];
                bl[nb * 2 + 1][0] = r4[2]; bl[nb * 2 + 1][1] = r4[3];
            }
            #pragma unroll
            for (int mi = 0; mi < 4; mi++)
                #pragma unroll
                for (int ni = 0; ni < 4; ni++) {
                    MMA(acc[mi][ni], ah[mi], bh[ni]);
                    MMA(acc[mi][ni], ah[mi], bl[ni]);
                    MMA(acc[mi][ni], al[mi], bh[ni]);
                }
        }
        __syncthreads();
        if (++st == NSTAGE) st = 0;
    }
#undef PREFETCH

    // ---- epilogue ----
    const int er = lane >> 2, ec = (lane & 3) * 2;
    if (EPI == 0) {
        float* Cz = Cf + (size_t)z * sC;
        #pragma unroll
        for (int mi = 0; mi < 4; mi++) {
            const int r1 = m0 + wm + mi * 16 + er;
            #pragma unroll
            for (int ni = 0; ni < 4; ni++) {
                const int c1 = n0 + wn + ni * 8 + ec;
                if (c1 < N) {
                    float2 v0 = make_float2(acc[mi][ni][0] * alpha, acc[mi][ni][1] * alpha);
                    float2 v1 = make_float2(acc[mi][ni][2] * alpha, acc[mi][ni][3] * alpha);
                    *(float2*)(Cz + (size_t)r1 * ldC + c1) = v0;
                    *(float2*)(Cz + (size_t)(r1 + 8) * ldC + c1) = v1;
                }
            }
        }
    } else {
        bf16* Ch = Chi + (size_t)z * sC;
        bf16* Cl = Clo + (size_t)z * sC;
        #pragma unroll
        for (int mi = 0; mi < 4; mi++) {
            const int r1 = m0 + wm + mi * 16 + er;
            #pragma unroll
            for (int ni = 0; ni < 4; ni++) {
                const int c1 = n0 + wn + ni * 8 + ec;
                if (c1 < N) {
                    bf16 h0, l0, h1, l1;
                    hlsplit(acc[mi][ni][0] * alpha, h0, l0);
                    hlsplit(acc[mi][ni][1] * alpha, h1, l1);
                    *(__nv_bfloat162*)(Ch + (size_t)r1 * ldC + c1) = __nv_bfloat162(h0, h1);
                    *(__nv_bfloat162*)(Cl + (size_t)r1 * ldC + c1) = __nv_bfloat162(l0, l1);
                    hlsplit(acc[mi][ni][2] * alpha, h0, l0);
                    hlsplit(acc[mi][ni][3] * alpha, h1, l1);
                    *(__nv_bfloat162*)(Ch + (size_t)(r1 + 8) * ldC + c1) = __nv_bfloat162(h0, h1);
                    *(__nv_bfloat162*)(Cl + (size_t)(r1 + 8) * ldC + c1) = __nv_bfloat162(l0, l1);
                }
            }
        }
    }
}

// ---------------- Launch ----------------
extern "C" void kernel_launch(void* const* d_in, const int* in_sizes, int n_in,
                              void* d_out, int out_size)
{
    (void)in_sizes; (void)n_in; (void)out_size;
    const float* x     = (const float*)d_in[0];
    const float* cosT  = (const float*)d_in[1];
    const float* sinT  = (const float*)d_in[2];
    const float* Wqkv  = (const float*)d_in[3];
    const float* Wqdec = (const float*)d_in[4];
    const float* Wout  = (const float*)d_in[5];
    float* out = (float*)d_out;

    float *lat, *qbuf, *scores;
    bf16 *xhi, *xlo, *wqkvThi, *wqkvTlo, *cqhi, *cqlo, *wqdecThi, *wqdecTlo;
    bf16 *qhi, *qlo, *khi, *klo, *vThi, *vTlo, *attnhi, *attnlo, *yhi, *ylo, *woutThi, *woutTlo;
    cudaGetSymbolAddress((void**)&lat, g_lat);
    cudaGetSymbolAddress((void**)&qbuf, g_qbuf);
    cudaGetSymbolAddress((void**)&scores, g_scores);
    cudaGetSymbolAddress((void**)&xhi, g_xhi);       cudaGetSymbolAddress((void**)&xlo, g_xlo);
    cudaGetSymbolAddress((void**)&wqkvThi, g_wqkvThi); cudaGetSymbolAddress((void**)&wqkvTlo, g_wqkvTlo);
    cudaGetSymbolAddress((void**)&cqhi, g_cqhi);     cudaGetSymbolAddress((void**)&cqlo, g_cqlo);
    cudaGetSymbolAddress((void**)&wqdecThi, g_wqdecThi); cudaGetSymbolAddress((void**)&wqdecTlo, g_wqdecTlo);
    cudaGetSymbolAddress((void**)&qhi, g_qhi);       cudaGetSymbolAddress((void**)&qlo, g_qlo);
    cudaGetSymbolAddress((void**)&khi, g_khi);       cudaGetSymbolAddress((void**)&klo, g_klo);
    cudaGetSymbolAddress((void**)&vThi, g_vThi);     cudaGetSymbolAddress((void**)&vTlo, g_vTlo);
    cudaGetSymbolAddress((void**)&attnhi, g_attnhi); cudaGetSymbolAddress((void**)&attnlo, g_attnlo);
    cudaGetSymbolAddress((void**)&yhi, g_yhi);       cudaGetSymbolAddress((void**)&ylo, g_ylo);
    cudaGetSymbolAddress((void**)&woutThi, g_woutThi); cudaGetSymbolAddress((void**)&woutTlo, g_woutTlo);

    cudaFuncSetAttribute((const void*)mmagemm<0, false, 0>,
                         cudaFuncAttributeMaxDynamicSharedMemorySize, SMEM_TOT);
    cudaFuncSetAttribute((const void*)mmagemm<1, false, 0>,
                         cudaFuncAttributeMaxDynamicSharedMemorySize, SMEM_TOT);
    cudaFuncSetAttribute((const void*)mmagemm<0, true, 1>,
                         cudaFuncAttributeMaxDynamicSharedMemorySize, SMEM_TOT);

    const float scale = 0.04419417382415922f;   // 1/sqrt(512)

    // 0-2: input conversions
    conv_x<<<8192, 256>>>(x, xhi, xlo);
    conv_wqkv<<<dim3(NPAD1 / 32, NEMBD / 32), 256>>>(Wqkv, wqkvThi, wqkvTlo);
    conv_w2<<<NQDBLK + NWOBLK, 256>>>(Wqdec, wqdecThi, wqdecTlo, Wout, woutThi, woutTlo);

    // 3: G1: lat = x @ Wqkv  [2048 x 1600]
    mmagemm<0, false, 0><<<dim3(13, 8, 1), 512, SMEM_TOT>>>(
        xhi, xlo, wqkvThi, wqkvTlo, lat, nullptr, nullptr,
        T_SEQ, LATD, NEMBD, NEMBD, NEMBD, LATD, 0, 0, 0, 1.f);

    // 4: conversions from lat (fused)
    conv_lat<<<NCQBLK + NVTBLK, 256>>>(lat, cqhi, cqlo, vThi, vTlo);

    // 5: G2: qbuf = c_q @ Wqdec  [2048 x 9216]
    mmagemm<0, false, 0><<<dim3(72, 8, 1), 512, SMEM_TOT>>>(
        cqhi, cqlo, wqdecThi, wqdecTlo, qbuf, nullptr, nullptr,
        T_SEQ, QTOT, QLOW, QLOW, QLOW, QTOT, 0, 0, 0, 1.f);

    // 6: RoPE + hi/lo q/k
    rope_pack_kernel<<<T_SEQ, 256>>>(lat, qbuf, cosT, sinT, khi, klo, qhi, qlo);

    // 7: scores[h] = scale * q_h @ k^T, causal tile skip
    mmagemm<1, false, 0><<<dim3(16, 8, NHEAD), 512, SMEM_TOT>>>(
        qhi, qlo, khi, klo, scores, nullptr, nullptr,
        T_SEQ, T_SEQ, QKHS, QTOT, QKHS, T_SEQ,
        (long)QKHS, 0, (long)T_SEQ * T_SEQ, scale);

    // 8: softmax -> hi/lo attn
    softmax_kernel<<<dim3(T_SEQ, NHEAD), 256>>>(scores, attnhi, attnlo);

    // 9: PV: y_h = attn_h @ v (K causal-truncated), bf16 hi/lo epilogue
    mmagemm<0, true, 1><<<dim3(4, 8, NHEAD), 512, SMEM_TOT>>>(
        attnhi, attnlo, vThi, vTlo, nullptr, yhi, ylo,
        T_SEQ, KVLOW, T_SEQ, T_SEQ, T_SEQ, YTOT,
        (long)T_SEQ * T_SEQ, 0, (long)KVLOW, 1.f);

    // 10: G3: out = y @ Wout  [2048 x 2048]
    mmagemm<0, false, 0><<<dim3(16, 8, 1), 512, SMEM_TOT>>>(
        yhi, ylo, woutThi, woutTlo, out, nullptr, nullptr,
        T_SEQ, NEMBD, YTOT, YTOT, YTOT, NEMBD, 0, 0, 0, 1.f);
}

// round 5
// speedup vs baseline: 3.5689x; 1.1281x over previous
#include <cuda_runtime.h>
#include <cuda_bf16.h>
#include <cstdint>

// ---------------- Problem constants ----------------
#define T_SEQ   2048
#define NEMBD   2048
#define NHEAD   16
#define KVLOW   512
#define QLOW    1024
#define ROPEHS  64
#define QKHS    576
#define LATD    1600
#define QTOT    9216
#define YTOT    8192
#define NPAD1   1664   // 1600 padded up to 13*128

typedef __nv_bfloat16 bf16;

// ---------------- Scratch (device globals; no allocations allowed) ----------------
__device__ float g_lat[(size_t)T_SEQ * LATD];
__device__ float g_qbuf[(size_t)T_SEQ * QTOT];
__device__ float g_scores[(size_t)NHEAD * T_SEQ * T_SEQ];

__device__ bf16 g_xhi[(size_t)T_SEQ * NEMBD];
__device__ bf16 g_xlo[(size_t)T_SEQ * NEMBD];
__device__ bf16 g_wqkvThi[(size_t)NPAD1 * NEMBD];
__device__ bf16 g_wqkvTlo[(size_t)NPAD1 * NEMBD];
__device__ bf16 g_cqhi[(size_t)T_SEQ * QLOW];
__device__ bf16 g_cqlo[(size_t)T_SEQ * QLOW];
__device__ bf16 g_wqdecThi[(size_t)QTOT * QLOW];
__device__ bf16 g_wqdecTlo[(size_t)QTOT * QLOW];
__device__ bf16 g_qhi[(size_t)T_SEQ * QTOT];
__device__ bf16 g_qlo[(size_t)T_SEQ * QTOT];
__device__ bf16 g_khi[(size_t)T_SEQ * QKHS];
__device__ bf16 g_klo[(size_t)T_SEQ * QKHS];
__device__ bf16 g_vThi[(size_t)KVLOW * T_SEQ];
__device__ bf16 g_vTlo[(size_t)KVLOW * T_SEQ];
__device__ bf16 g_attnhi[(size_t)NHEAD * T_SEQ * T_SEQ];
__device__ bf16 g_attnlo[(size_t)NHEAD * T_SEQ * T_SEQ];
__device__ bf16 g_yhi[(size_t)T_SEQ * YTOT];
__device__ bf16 g_ylo[(size_t)T_SEQ * YTOT];
__device__ bf16 g_woutThi[(size_t)NEMBD * YTOT];
__device__ bf16 g_woutTlo[(size_t)NEMBD * YTOT];

// ---------------- helpers ----------------
__device__ __forceinline__ void hlsplit(float v, bf16& h, bf16& l) {
    h = __float2bfloat16(v);
    l = __float2bfloat16(v - __bfloat162float(h));
}
__device__ __forceinline__ uint32_t smem_u32(const void* p) {
    uint32_t a;
    asm("{ .reg .u64 t; cvta.to.shared.u64 t, %1; cvt.u32.u64 %0, t; }" : "=r"(a) : "l"(p));
    return a;
}

#define CPA(dst, src) \
    asm volatile("cp.async.cg.shared.global [%0], [%1], 16;\n" :: "r"(dst), "l"(src))
#define CP_COMMIT() asm volatile("cp.async.commit_group;\n" ::: "memory")
#define CP_WAIT(N)  asm volatile("cp.async.wait_group %0;\n" :: "n"(N) : "memory")

#define LDSM4(r, addr) \
    asm volatile("ldmatrix.sync.aligned.m8n8.x4.shared.b16 {%0,%1,%2,%3}, [%4];" \
        : "=r"((r)[0]), "=r"((r)[1]), "=r"((r)[2]), "=r"((r)[3]) : "r"(addr))

#define MMA(d, a, b) \
    asm volatile("mma.sync.aligned.m16n8k16.row.col.f32.bf16.bf16.f32 " \
        "{%0,%1,%2,%3}, {%4,%5,%6,%7}, {%8,%9}, {%0,%1,%2,%3};" \
        : "+f"((d)[0]), "+f"((d)[1]), "+f"((d)[2]), "+f"((d)[3]) \
        : "r"((a)[0]), "r"((a)[1]), "r"((a)[2]), "r"((a)[3]), "r"((b)[0]), "r"((b)[1]))

// ---------------- Conversion bodies ----------------
__device__ __forceinline__ void convpack_body(const float* __restrict__ in,
                                              bf16* __restrict__ hi, bf16* __restrict__ lo,
                                              int R, int C, int ldin, size_t idx)
{
    int half = C >> 1;
    if (idx >= (size_t)R * half) return;
    int r = (int)(idx / half);
    int c = (int)(idx - (size_t)r * half) * 2;
    float v0 = in[(size_t)r * ldin + c];
    float v1 = in[(size_t)r * ldin + c + 1];
    bf16 h0, l0, h1, l1;
    hlsplit(v0, h0, l0); hlsplit(v1, h1, l1);
    *(__nv_bfloat162*)(hi + (size_t)r * C + c) = __nv_bfloat162(h0, h1);
    *(__nv_bfloat162*)(lo + (size_t)r * C + c) = __nv_bfloat162(l0, l1);
}

__device__ __forceinline__ void cvT_body(const float* __restrict__ in,
                                         bf16* __restrict__ hi, bf16* __restrict__ lo,
                                         int R, int C, int ldin, int bx, int by,
                                         int tid, float (*ts)[33])
{
    const int c0 = bx * 32, r0 = by * 32;
    const int j = tid & 31;
    #pragma unroll
    for (int q = 0; q < 4; q++) {
        int i = (tid >> 5) + q * 8;
        ts[j][i] = (c0 + j < C) ? in[(size_t)(r0 + i) * ldin + (c0 + j)] : 0.f;
    }
    __syncthreads();
    const int cl = tid >> 3, g = tid & 7;
    bf16 h[4], l[4];
    #pragma unroll
    for (int q = 0; q < 4; q++) hlsplit(ts[cl][g * 4 + q], h[q], l[q]);
    size_t base = (size_t)(c0 + cl) * R + r0 + g * 4;
    *(__nv_bfloat162*)(hi + base)     = __nv_bfloat162(h[0], h[1]);
    *(__nv_bfloat162*)(hi + base + 2) = __nv_bfloat162(h[2], h[3]);
    *(__nv_bfloat162*)(lo + base)     = __nv_bfloat162(l[0], l[1]);
    *(__nv_bfloat162*)(lo + base + 2) = __nv_bfloat162(l[2], l[3]);
}

// launch 0: x -> hi/lo
__global__ void conv_x(const float* __restrict__ x, bf16* __restrict__ hi, bf16* __restrict__ lo)
{
    convpack_body(x, hi, lo, T_SEQ, NEMBD, NEMBD, (size_t)blockIdx.x * 256 + threadIdx.x);
}
// launch 1: WqkvT
__global__ void conv_wqkv(const float* __restrict__ w, bf16* __restrict__ hi, bf16* __restrict__ lo)
{
    __shared__ float ts[32][33];
    cvT_body(w, hi, lo, NEMBD, LATD, LATD, blockIdx.x, blockIdx.y, threadIdx.x, ts);
}
// launch 2: fused WqdecT + WoutT
#define NQDBLK ((QTOT / 32) * (QLOW / 32))      // 9216
#define NWOBLK ((NEMBD / 32) * (YTOT / 32))     // 16384
__global__ void conv_w2(const float* __restrict__ wqdec, bf16* __restrict__ qdhi, bf16* __restrict__ qdlo,
                        const float* __restrict__ wout, bf16* __restrict__ wohi, bf16* __restrict__ wolo)
{
    __shared__ float ts[32][33];
    int b = blockIdx.x;
    if (b < NQDBLK) {
        cvT_body(wqdec, qdhi, qdlo, QLOW, QTOT, QTOT, b % (QTOT / 32), b / (QTOT / 32), threadIdx.x, ts);
    } else {
        b -= NQDBLK;
        cvT_body(wout, wohi, wolo, YTOT, NEMBD, NEMBD, b % (NEMBD / 32), b / (NEMBD / 32), threadIdx.x, ts);
    }
}
// launch 4: fused cq convpack + vT transpose (both read lat)
#define NCQBLK 4096                              // 2048*1024/2/256
#define NVTBLK ((KVLOW / 32) * (T_SEQ / 32))     // 1024
__global__ void conv_lat(const float* __restrict__ lat,
                         bf16* __restrict__ cqhi, bf16* __restrict__ cqlo,
                         bf16* __restrict__ vthi, bf16* __restrict__ vtlo)
{
    __shared__ float ts[32][33];
    int b = blockIdx.x;
    if (b < NCQBLK) {
        convpack_body(lat + (KVLOW + ROPEHS), cqhi, cqlo, T_SEQ, QLOW, LATD,
                      (size_t)b * 256 + threadIdx.x);
    } else {
        b -= NCQBLK;
        cvT_body(lat, vthi, vtlo, T_SEQ, KVLOW, LATD, b % (KVLOW / 32), b / (KVLOW / 32),
                 threadIdx.x, ts);
    }
}

// ---------------- RoPE + hi/lo pack of q and k ----------------
__global__ void rope_pack_kernel(const float* __restrict__ lat, const float* __restrict__ qbuf,
                                 const float* __restrict__ cosT, const float* __restrict__ sinT,
                                 bf16* __restrict__ khi, bf16* __restrict__ klo,
                                 bf16* __restrict__ qhi, bf16* __restrict__ qlo)
{
    const int t = blockIdx.x, tid = threadIdx.x;
    __shared__ float cs[ROPEHS], sn[ROPEHS];
    if (tid < ROPEHS) {
        cs[tid] = cosT[(size_t)t * ROPEHS + tid];
        sn[tid] = sinT[(size_t)t * ROPEHS + tid];
    }
    __syncthreads();

    const float* lrow = lat + (size_t)t * LATD;
    bf16* krh = khi + (size_t)t * QKHS;
    bf16* krl = klo + (size_t)t * QKHS;
    for (int p = tid; p < QKHS / 2; p += 256) {
        int e = p * 2;
        float v[2];
        #pragma unroll
        for (int u = 0; u < 2; u++) {
            int ee = e + u;
            if (ee < KVLOW) v[u] = lrow[ee];
            else {
                int i2 = ee - KVLOW;
                float xv = lrow[ee];
                v[u] = (i2 < 32) ? xv * cs[i2] - lrow[ee + 32] * sn[i2]
                                 : xv * cs[i2] + lrow[ee - 32] * sn[i2];
            }
        }
        bf16 h0, l0, h1, l1;
        hlsplit(v[0], h0, l0); hlsplit(v[1], h1, l1);
        *(__nv_bfloat162*)(krh + e) = __nv_bfloat162(h0, h1);
        *(__nv_bfloat162*)(krl + e) = __nv_bfloat162(l0, l1);
    }

    const float* qrow = qbuf + (size_t)t * QTOT;
    bf16* qrh = qhi + (size_t)t * QTOT;
    bf16* qrl = qlo + (size_t)t * QTOT;
    for (int p = tid; p < QTOT / 2; p += 256) {
        int e = p * 2;
        float v[2];
        #pragma unroll
        for (int u = 0; u < 2; u++) {
            int ee = e + u;
            int hh = ee / QKHS;
            int i = ee - hh * QKHS;
            if (i < KVLOW) v[u] = qrow[ee];
            else {
                int i2 = i - KVLOW;
                float xv = qrow[ee];
                v[u] = (i2 < 32) ? xv * cs[i2] - qrow[ee + 32] * sn[i2]
                                 : xv * cs[i2] + qrow[ee - 32] * sn[i2];
            }
        }
        bf16 h0, l0, h1, l1;
        hlsplit(v[0], h0, l0); hlsplit(v[1], h1, l1);
        *(__nv_bfloat162*)(qrh + e) = __nv_bfloat162(h0, h1);
        *(__nv_bfloat162*)(qrl + e) = __nv_bfloat162(l0, l1);
    }
}

// ---------------- Softmax -> hi/lo attn (zero-filled to 128-boundary) ----------------
__global__ __launch_bounds__(256)
void softmax_kernel(const float* __restrict__ scores,
                    bf16* __restrict__ ahi, bf16* __restrict__ alo)
{
    __shared__ float srow[T_SEQ];
    __shared__ float red[8];
    const int t = blockIdx.x, h = blockIdx.y, tid = threadIdx.x;
    const float* row = scores + ((size_t)h * T_SEQ + t) * T_SEQ;
    const int n = t + 1;

    float m = -3.4e38f;
    for (int s = tid; s < n; s += 256) { float v = row[s]; srow[s] = v; m = fmaxf(m, v); }
    #pragma unroll
    for (int o = 16; o; o >>= 1) m = fmaxf(m, __shfl_xor_sync(0xffffffffu, m, o));
    if ((tid & 31) == 0) red[tid >> 5] = m;
    __syncthreads();
    float mmax = red[0];
    #pragma unroll
    for (int i = 1; i < 8; i++) mmax = fmaxf(mmax, red[i]);
    __syncthreads();

    float sum = 0.f;
    for (int s = tid; s < n; s += 256) { float e = __expf(srow[s] - mmax); srow[s] = e; sum += e; }
    #pragma unroll
    for (int o = 16; o; o >>= 1) sum += __shfl_xor_sync(0xffffffffu, sum, o);
    if ((tid & 31) == 0) red[tid >> 5] = sum;
    __syncthreads();
    float total = 0.f;
    #pragma unroll
    for (int i = 0; i < 8; i++) total += red[i];
    const float inv = 1.f / total;

    bf16* rh = ahi + ((size_t)h * T_SEQ + t) * T_SEQ;
    bf16* rl = alo + ((size_t)h * T_SEQ + t) * T_SEQ;
    const int kpad = ((t >> 7) + 1) << 7;   // 128-granular for PV K truncation
    for (int p = tid; p < (kpad >> 1); p += 256) {
        int s0 = 2 * p;
        float v0 = (s0 <= t) ? srow[s0] * inv : 0.f;
        float v1 = (s0 + 1 <= t) ? srow[s0 + 1] * inv : 0.f;
        bf16 h0, l0, h1, l1;
        hlsplit(v0, h0, l0); hlsplit(v1, h1, l1);
        *(__nv_bfloat162*)(rh + s0) = __nv_bfloat162(h0, h1);
        *(__nv_bfloat162*)(rl + s0) = __nv_bfloat162(l0, l1);
    }
}

// ---------------- mma.sync GEMM: C = alpha * A * B^T ----------------
// CTA tile 128x128, 256 threads (8 warps, 2m x 4n of 64x32), BK=32,
// 3-stage pipeline, compact XOR-swizzled smem (64B rows, no padding),
// one __syncthreads per chunk, 2 CTAs/SM.
#define TILEB  8192                 // 128 rows x 64B
#define STAGEB (4 * TILEB)          // 32768: Ahi, Alo, Bhi, Blo
#define NSTAGE 3
#define SMEM_TOT (NSTAGE * STAGEB)  // 98304

template<int CSKIP, bool CK, int EPI>   // EPI: 0 -> f32 C, 1 -> hi/lo bf16 C
__global__ __launch_bounds__(256, 2)
void mmagemm(const bf16* __restrict__ Ahi, const bf16* __restrict__ Alo,
             const bf16* __restrict__ Bhi, const bf16* __restrict__ Blo,
             float* __restrict__ Cf, bf16* __restrict__ Chi, bf16* __restrict__ Clo,
             int M, int N, int K, int ldA, int ldB, int ldC,
             long sA, long sB, long sC, float alpha)
{
    extern __shared__ char smc[];
    const int bx = blockIdx.x, by = blockIdx.y, z = blockIdx.z;
    if (CSKIP && bx > by) return;   // tile fully above causal diagonal

    Ahi += (size_t)z * sA;  Alo += (size_t)z * sA;
    Bhi += (size_t)z * sB;  Blo += (size_t)z * sB;

    const int Keff = CK ? min(K, (by + 1) * 128) : K;
    const int nc = Keff >> 5;
    const int tid = threadIdx.x, wid = tid >> 5, lane = tid & 31;
    const int m0 = by * 128, n0 = bx * 128;
    const uint32_t smb = smem_u32(smc);

    // ---- load mapping: thread -> row tid>>1, chunks {(tid&1)*2, (tid&1)*2+1} ----
    const int lrow = tid >> 1;
    const int lc0  = (tid & 1) * 2;                 // first 16B chunk index
    const int lswz = (lrow >> 1) & 3;
    const uint32_t dRow = (uint32_t)(lrow * 64);
    const uint32_t d0 = dRow + (uint32_t)((lc0 ^ lswz) << 4);
    const uint32_t d1 = dRow + (uint32_t)(((lc0 + 1) ^ lswz) << 4);
    const bf16* gAh = Ahi + (size_t)(m0 + lrow) * ldA + lc0 * 8;
    const bf16* gAl = Alo + (size_t)(m0 + lrow) * ldA + lc0 * 8;
    const bf16* gBh = Bhi + (size_t)(n0 + lrow) * ldB + lc0 * 8;
    const bf16* gBl = Blo + (size_t)(n0 + lrow) * ldB + lc0 * 8;

#define PREFETCH(c, s) do { \
        uint32_t b_ = smb + (uint32_t)(s) * STAGEB; \
        const bf16* p_ = gAh + (size_t)(c) * 32; \
        CPA(b_ + d0, p_); CPA(b_ + d1, p_ + 8); \
        p_ = gAl + (size_t)(c) * 32; \
        CPA(b_ + TILEB + d0, p_); CPA(b_ + TILEB + d1, p_ + 8); \
        p_ = gBh + (size_t)(c) * 32; \
        CPA(b_ + 2 * TILEB + d0, p_); CPA(b_ + 2 * TILEB + d1, p_ + 8); \
        p_ = gBl + (size_t)(c) * 32; \
        CPA(b_ + 3 * TILEB + d0, p_); CPA(b_ + 3 * TILEB + d1, p_ + 8); \
        CP_COMMIT(); \
    } while (0)

    // ---- compute mapping: warp tile 64x32 (2m x 4n warps) ----
    const int wm = (wid & 1) * 64;
    const int wn = (wid >> 1) * 32;
    // A: row = wm + mi*16 + (lane&15); 16B chunk = half*2 + (lane>>4)
    const int aRowL = lane & 15;
    const int aSwz = (aRowL >> 1) & 3;
    const int aCh = lane >> 4;
    const uint32_t aBase = (uint32_t)((wm + aRowL) * 64);
    // B: row = wn + nb*16 + (lane&7) + ((lane&16)>>1); chunk = half*2 + ((lane&8)>>3)
    const int bRowL = (lane & 7) + ((lane & 16) >> 1);
    const int bSwz = (bRowL >> 1) & 3;
    const int bCh = (lane & 8) >> 3;
    const uint32_t bBase = (uint32_t)((wn + bRowL) * 64);

    float acc[4][4][4];
    #pragma unroll
    for (int i = 0; i < 4; i++)
        #pragma unroll
        for (int j = 0; j < 4; j++)
            #pragma unroll
            for (int q = 0; q < 4; q++) acc[i][j][q] = 0.f;

    PREFETCH(0, 0);
    if (nc > 1) PREFETCH(1, 1);

    int st = 0;
    for (int c = 0; c < nc; ++c) {
        if (c + 1 < nc) CP_WAIT(1); else CP_WAIT(0);
        __syncthreads();
        if (c + 2 < nc) {
            int ps = st + 2; if (ps >= NSTAGE) ps -= NSTAGE;
            PREFETCH(c + 2, ps);
        }

        const uint32_t base = smb + (uint32_t)st * STAGEB;
        #pragma unroll
        for (int half = 0; half < 2; half++) {
            const uint32_t aCol = (uint32_t)(((half * 2 + aCh) ^ aSwz) << 4);
            const uint32_t bCol = (uint32_t)(((half * 2 + bCh) ^ bSwz) << 4);
            uint32_t ah[4][4], al[4][4];
            #pragma unroll
            for (int mi = 0; mi < 4; mi++) {
                LDSM4(ah[mi], base + aBase + mi * 1024 + aCol);
                LDSM4(al[mi], base + TILEB + aBase + mi * 1024 + aCol);
            }
            uint32_t bh[4][2], bl[4][2];
            #pragma unroll
            for (int nb = 0; nb < 2; nb++) {
                uint32_t r4[4];
                LDSM4(r4, base + 2 * TILEB + bBase + nb * 1024 + bCol);
                bh[nb * 2][0] = r4[0]; bh[nb * 2][1] = r4[1];
                bh[nb * 2 + 1][0] = r4[2]; bh[nb * 2 + 1][1] = r4[3];
                LDSM4(r4, base + 3 * TILEB + bBase + nb * 1024 + bCol);
                bl[nb * 2][0] = r4[0]; bl[nb * 2][1] = r4[1];
                bl[nb * 2 + 1][0] = r4[2]; bl[nb * 2 + 1][1] = r4[3];
            }
            #pragma unroll
            for (int mi = 0; mi < 4; mi++)
                #pragma unroll
                for (int ni = 0; ni < 4; ni++) {
                    MMA(acc[mi][ni], ah[mi], bh[ni]);
                    MMA(acc[mi][ni], ah[mi], bl[ni]);
                    MMA(acc[mi][ni], al[mi], bh[ni]);
                }
        }
        if (++st == NSTAGE) st = 0;
    }
#undef PREFETCH

    // ---- epilogue ----
    const int er = lane >> 2, ec = (lane & 3) * 2;
    if (EPI == 0) {
        float* Cz = Cf + (size_t)z * sC;
        #pragma unroll
        for (int mi = 0; mi < 4; mi++) {
            const int r1 = m0 + wm + mi * 16 + er;
            #pragma unroll
            for (int ni = 0; ni < 4; ni++) {
                const int c1 = n0 + wn + ni * 8 + ec;
                if (c1 < N) {
                    float2 v0 = make_float2(acc[mi][ni][0] * alpha, acc[mi][ni][1] * alpha);
                    float2 v1 = make_float2(acc[mi][ni][2] * alpha, acc[mi][ni][3] * alpha);
                    *(float2*)(Cz + (size_t)r1 * ldC + c1) = v0;
                    *(float2*)(Cz + (size_t)(r1 + 8) * ldC + c1) = v1;
                }
            }
        }
    } else {
        bf16* Ch = Chi + (size_t)z * sC;
        bf16* Cl = Clo + (size_t)z * sC;
        #pragma unroll
        for (int mi = 0; mi < 4; mi++) {
            const int r1 = m0 + wm + mi * 16 + er;
            #pragma unroll
            for (int ni = 0; ni < 4; ni++) {
                const int c1 = n0 + wn + ni * 8 + ec;
                if (c1 < N) {
                    bf16 h0, l0, h1, l1;
                    hlsplit(acc[mi][ni][0] * alpha, h0, l0);
                    hlsplit(acc[mi][ni][1] * alpha, h1, l1);
                    *(__nv_bfloat162*)(Ch + (size_t)r1 * ldC + c1) = __nv_bfloat162(h0, h1);
                    *(__nv_bfloat162*)(Cl + (size_t)r1 * ldC + c1) = __nv_bfloat162(l0, l1);
                    hlsplit(acc[mi][ni][2] * alpha, h0, l0);
                    hlsplit(acc[mi][ni][3] * alpha, h1, l1);
                    *(__nv_bfloat162*)(Ch + (size_t)(r1 + 8) * ldC + c1) = __nv_bfloat162(h0, h1);
                    *(__nv_bfloat162*)(Cl + (size_t)(r1 + 8) * ldC + c1) = __nv_bfloat162(l0, l1);
                }
            }
        }
    }
}

// ---------------- Launch ----------------
extern "C" void kernel_launch(void* const* d_in, const int* in_sizes, int n_in,
                              void* d_out, int out_size)
{
    (void)in_sizes; (void)n_in; (void)out_size;
    const float* x     = (const float*)d_in[0];
    const float* cosT  = (const float*)d_in[1];
    const float* sinT  = (const float*)d_in[2];
    const float* Wqkv  = (const float*)d_in[3];
    const float* Wqdec = (const float*)d_in[4];
    const float* Wout  = (const float*)d_in[5];
    float* out = (float*)d_out;

    float *lat, *qbuf, *scores;
    bf16 *xhi, *xlo, *wqkvThi, *wqkvTlo, *cqhi, *cqlo, *wqdecThi, *wqdecTlo;
    bf16 *qhi, *qlo, *khi, *klo, *vThi, *vTlo, *attnhi, *attnlo, *yhi, *ylo, *woutThi, *woutTlo;
    cudaGetSymbolAddress((void**)&lat, g_lat);
    cudaGetSymbolAddress((void**)&qbuf, g_qbuf);
    cudaGetSymbolAddress((void**)&scores, g_scores);
    cudaGetSymbolAddress((void**)&xhi, g_xhi);       cudaGetSymbolAddress((void**)&xlo, g_xlo);
    cudaGetSymbolAddress((void**)&wqkvThi, g_wqkvThi); cudaGetSymbolAddress((void**)&wqkvTlo, g_wqkvTlo);
    cudaGetSymbolAddress((void**)&cqhi, g_cqhi);     cudaGetSymbolAddress((void**)&cqlo, g_cqlo);
    cudaGetSymbolAddress((void**)&wqdecThi, g_wqdecThi); cudaGetSymbolAddress((void**)&wqdecTlo, g_wqdecTlo);
    cudaGetSymbolAddress((void**)&qhi, g_qhi);       cudaGetSymbolAddress((void**)&qlo, g_qlo);
    cudaGetSymbolAddress((void**)&khi, g_khi);       cudaGetSymbolAddress((void**)&klo, g_klo);
    cudaGetSymbolAddress((void**)&vThi, g_vThi);     cudaGetSymbolAddress((void**)&vTlo, g_vTlo);
    cudaGetSymbolAddress((void**)&attnhi, g_attnhi); cudaGetSymbolAddress((void**)&attnlo, g_attnlo);
    cudaGetSymbolAddress((void**)&yhi, g_yhi);       cudaGetSymbolAddress((void**)&ylo, g_ylo);
    cudaGetSymbolAddress((void**)&woutThi, g_woutThi); cudaGetSymbolAddress((void**)&woutTlo, g_woutTlo);

    cudaFuncSetAttribute((const void*)mmagemm<0, false, 0>,
                         cudaFuncAttributeMaxDynamicSharedMemorySize, SMEM_TOT);
    cudaFuncSetAttribute((const void*)mmagemm<1, false, 0>,
                         cudaFuncAttributeMaxDynamicSharedMemorySize, SMEM_TOT);
    cudaFuncSetAttribute((const void*)mmagemm<0, true, 1>,
                         cudaFuncAttributeMaxDynamicSharedMemorySize, SMEM_TOT);

    const float scale = 0.04419417382415922f;   // 1/sqrt(512)

    // 0-2: input conversions
    conv_x<<<8192, 256>>>(x, xhi, xlo);
    conv_wqkv<<<dim3(NPAD1 / 32, NEMBD / 32), 256>>>(Wqkv, wqkvThi, wqkvTlo);
    conv_w2<<<NQDBLK + NWOBLK, 256>>>(Wqdec, wqdecThi, wqdecTlo, Wout, woutThi, woutTlo);

    // 3: G1: lat = x @ Wqkv  [2048 x 1600]
    mmagemm<0, false, 0><<<dim3(13, 16, 1), 256, SMEM_TOT>>>(
        xhi, xlo, wqkvThi, wqkvTlo, lat, nullptr, nullptr,
        T_SEQ, LATD, NEMBD, NEMBD, NEMBD, LATD, 0, 0, 0, 1.f);

    // 4: conversions from lat (fused)
    conv_lat<<<NCQBLK + NVTBLK, 256>>>(lat, cqhi, cqlo, vThi, vTlo);

    // 5: G2: qbuf = c_q @ Wqdec  [2048 x 9216]
    mmagemm<0, false, 0><<<dim3(72, 16, 1), 256, SMEM_TOT>>>(
        cqhi, cqlo, wqdecThi, wqdecTlo, qbuf, nullptr, nullptr,
        T_SEQ, QTOT, QLOW, QLOW, QLOW, QTOT, 0, 0, 0, 1.f);

    // 6: RoPE + hi/lo q/k
    rope_pack_kernel<<<T_SEQ, 256>>>(lat, qbuf, cosT, sinT, khi, klo, qhi, qlo);

    // 7: scores[h] = scale * q_h @ k^T, causal tile skip
    mmagemm<1, false, 0><<<dim3(16, 16, NHEAD), 256, SMEM_TOT>>>(
        qhi, qlo, khi, klo, scores, nullptr, nullptr,
        T_SEQ, T_SEQ, QKHS, QTOT, QKHS, T_SEQ,
        (long)QKHS, 0, (long)T_SEQ * T_SEQ, scale);

    // 8: softmax -> hi/lo attn
    softmax_kernel<<<dim3(T_SEQ, NHEAD), 256>>>(scores, attnhi, attnlo);

    // 9: PV: y_h = attn_h @ v (K causal-truncated), bf16 hi/lo epilogue
    mmagemm<0, true, 1><<<dim3(4, 16, NHEAD), 256, SMEM_TOT>>>(
        attnhi, attnlo, vThi, vTlo, nullptr, yhi, ylo,
        T_SEQ, KVLOW, T_SEQ, T_SEQ, T_SEQ, YTOT,
        (long)T_SEQ * T_SEQ, 0, (long)KVLOW, 1.f);

    // 10: G3: out = y @ Wout  [2048 x 2048]
    mmagemm<0, false, 0><<<dim3(16, 16, 1), 256, SMEM_TOT>>>(
        yhi, ylo, woutThi, woutTlo, out, nullptr, nullptr,
        T_SEQ, NEMBD, YTOT, YTOT, YTOT, NEMBD, 0, 0, 0, 1.f);
}

// round 8
// speedup vs baseline: 3.5887x; 1.0056x over previous
#include <cuda_runtime.h>
#include <cuda_bf16.h>
#include <cstdint>

// ---------------- Problem constants ----------------
#define T_SEQ   2048
#define NEMBD   2048
#define NHEAD   16
#define KVLOW   512
#define QLOW    1024
#define ROPEHS  64
#define QKHS    576
#define LATD    1600
#define QTOT    9216
#define YTOT    8192
#define NPAD1   1664   // 1600 padded up to 13*128

typedef __nv_bfloat16 bf16;

// ---------------- Scratch (device globals; no allocations allowed) ----------------
__device__ float g_lat[(size_t)T_SEQ * LATD];
__device__ float g_qbuf[(size_t)T_SEQ * QTOT];
__device__ float g_scores[(size_t)NHEAD * T_SEQ * T_SEQ];

__device__ bf16 g_xhi[(size_t)T_SEQ * NEMBD];
__device__ bf16 g_xlo[(size_t)T_SEQ * NEMBD];
__device__ bf16 g_wqkvThi[(size_t)NPAD1 * NEMBD];
__device__ bf16 g_wqkvTlo[(size_t)NPAD1 * NEMBD];
__device__ bf16 g_cqhi[(size_t)T_SEQ * QLOW];
__device__ bf16 g_cqlo[(size_t)T_SEQ * QLOW];
__device__ bf16 g_wqdecThi[(size_t)QTOT * QLOW];
__device__ bf16 g_wqdecTlo[(size_t)QTOT * QLOW];
__device__ bf16 g_qhi[(size_t)T_SEQ * QTOT];
__device__ bf16 g_qlo[(size_t)T_SEQ * QTOT];
__device__ bf16 g_khi[(size_t)T_SEQ * QKHS];
__device__ bf16 g_klo[(size_t)T_SEQ * QKHS];
__device__ bf16 g_vThi[(size_t)KVLOW * T_SEQ];
__device__ bf16 g_vTlo[(size_t)KVLOW * T_SEQ];
__device__ bf16 g_attnhi[(size_t)NHEAD * T_SEQ * T_SEQ];
__device__ bf16 g_attnlo[(size_t)NHEAD * T_SEQ * T_SEQ];
__device__ bf16 g_yhi[(size_t)T_SEQ * YTOT];
__device__ bf16 g_ylo[(size_t)T_SEQ * YTOT];
__device__ bf16 g_woutThi[(size_t)NEMBD * YTOT];
__device__ bf16 g_woutTlo[(size_t)NEMBD * YTOT];

// ---------------- helpers ----------------
__device__ __forceinline__ void hlsplit(float v, bf16& h, bf16& l) {
    h = __float2bfloat16(v);
    l = __float2bfloat16(v - __bfloat162float(h));
}
__device__ __forceinline__ uint32_t smem_u32(const void* p) {
    uint32_t a;
    asm("{ .reg .u64 t; cvta.to.shared.u64 t, %1; cvt.u32.u64 %0, t; }" : "=r"(a) : "l"(p));
    return a;
}

#define CPA(dst, src) \
    asm volatile("cp.async.cg.shared.global [%0], [%1], 16;\n" :: "r"(dst), "l"(src))
#define CP_COMMIT() asm volatile("cp.async.commit_group;\n" ::: "memory")
#define CP_WAIT(N)  asm volatile("cp.async.wait_group %0;\n" :: "n"(N) : "memory")

#define LDSM4(r, addr) \
    asm volatile("ldmatrix.sync.aligned.m8n8.x4.shared.b16 {%0,%1,%2,%3}, [%4];" \
        : "=r"((r)[0]), "=r"((r)[1]), "=r"((r)[2]), "=r"((r)[3]) : "r"(addr))

#define MMA(d, a, b) \
    asm volatile("mma.sync.aligned.m16n8k16.row.col.f32.bf16.bf16.f32 " \
        "{%0,%1,%2,%3}, {%4,%5,%6,%7}, {%8,%9}, {%0,%1,%2,%3};" \
        : "+f"((d)[0]), "+f"((d)[1]), "+f"((d)[2]), "+f"((d)[3]) \
        : "r"((a)[0]), "r"((a)[1]), "r"((a)[2]), "r"((a)[3]), "r"((b)[0]), "r"((b)[1]))

// ---------------- Conversion bodies ----------------
__device__ __forceinline__ void convpack_body(const float* __restrict__ in,
                                              bf16* __restrict__ hi, bf16* __restrict__ lo,
                                              int R, int C, int ldin, size_t idx)
{
    int half = C >> 1;
    if (idx >= (size_t)R * half) return;
    int r = (int)(idx / half);
    int c = (int)(idx - (size_t)r * half) * 2;
    float v0 = in[(size_t)r * ldin + c];
    float v1 = in[(size_t)r * ldin + c + 1];
    bf16 h0, l0, h1, l1;
    hlsplit(v0, h0, l0); hlsplit(v1, h1, l1);
    *(__nv_bfloat162*)(hi + (size_t)r * C + c) = __nv_bfloat162(h0, h1);
    *(__nv_bfloat162*)(lo + (size_t)r * C + c) = __nv_bfloat162(l0, l1);
}

__device__ __forceinline__ void cvT_body(const float* __restrict__ in,
                                         bf16* __restrict__ hi, bf16* __restrict__ lo,
                                         int R, int C, int ldin, int bx, int by,
                                         int tid, float (*ts)[33])
{
    const int c0 = bx * 32, r0 = by * 32;
    const int j = tid & 31;
    #pragma unroll
    for (int q = 0; q < 4; q++) {
        int i = (tid >> 5) + q * 8;
        ts[j][i] = (c0 + j < C) ? in[(size_t)(r0 + i) * ldin + (c0 + j)] : 0.f;
    }
    __syncthreads();
    const int cl = tid >> 3, g = tid & 7;
    bf16 h[4], l[4];
    #pragma unroll
    for (int q = 0; q < 4; q++) hlsplit(ts[cl][g * 4 + q], h[q], l[q]);
    size_t base = (size_t)(c0 + cl) * R + r0 + g * 4;
    *(__nv_bfloat162*)(hi + base)     = __nv_bfloat162(h[0], h[1]);
    *(__nv_bfloat162*)(hi + base + 2) = __nv_bfloat162(h[2], h[3]);
    *(__nv_bfloat162*)(lo + base)     = __nv_bfloat162(l[0], l[1]);
    *(__nv_bfloat162*)(lo + base + 2) = __nv_bfloat162(l[2], l[3]);
}

// launch 0: x -> hi/lo
__global__ void conv_x(const float* __restrict__ x, bf16* __restrict__ hi, bf16* __restrict__ lo)
{
    convpack_body(x, hi, lo, T_SEQ, NEMBD, NEMBD, (size_t)blockIdx.x * 256 + threadIdx.x);
}
// launch 1: WqkvT
__global__ void conv_wqkv(const float* __restrict__ w, bf16* __restrict__ hi, bf16* __restrict__ lo)
{
    __shared__ float ts[32][33];
    cvT_body(w, hi, lo, NEMBD, LATD, LATD, blockIdx.x, blockIdx.y, threadIdx.x, ts);
}
// launch 2: fused WqdecT + WoutT
#define NQDBLK ((QTOT / 32) * (QLOW / 32))      // 9216
#define NWOBLK ((NEMBD / 32) * (YTOT / 32))     // 16384
__global__ void conv_w2(const float* __restrict__ wqdec, bf16* __restrict__ qdhi, bf16* __restrict__ qdlo,
                        const float* __restrict__ wout, bf16* __restrict__ wohi, bf16* __restrict__ wolo)
{
    __shared__ float ts[32][33];
    int b = blockIdx.x;
    if (b < NQDBLK) {
        cvT_body(wqdec, qdhi, qdlo, QLOW, QTOT, QTOT, b % (QTOT / 32), b / (QTOT / 32), threadIdx.x, ts);
    } else {
        b -= NQDBLK;
        cvT_body(wout, wohi, wolo, YTOT, NEMBD, NEMBD, b % (NEMBD / 32), b / (NEMBD / 32), threadIdx.x, ts);
    }
}
// launch 4: fused cq convpack + vT transpose (both read lat)
#define NCQBLK 4096                              // 2048*1024/2/256
#define NVTBLK ((KVLOW / 32) * (T_SEQ / 32))     // 1024
__global__ void conv_lat(const float* __restrict__ lat,
                         bf16* __restrict__ cqhi, bf16* __restrict__ cqlo,
                         bf16* __restrict__ vthi, bf16* __restrict__ vtlo)
{
    __shared__ float ts[32][33];
    int b = blockIdx.x;
    if (b < NCQBLK) {
        convpack_body(lat + (KVLOW + ROPEHS), cqhi, cqlo, T_SEQ, QLOW, LATD,
                      (size_t)b * 256 + threadIdx.x);
    } else {
        b -= NCQBLK;
        cvT_body(lat, vthi, vtlo, T_SEQ, KVLOW, LATD, b % (KVLOW / 32), b / (KVLOW / 32),
                 threadIdx.x, ts);
    }
}

// ---------------- RoPE + hi/lo pack of q and k ----------------
__global__ void rope_pack_kernel(const float* __restrict__ lat, const float* __restrict__ qbuf,
                                 const float* __restrict__ cosT, const float* __restrict__ sinT,
                                 bf16* __restrict__ khi, bf16* __restrict__ klo,
                                 bf16* __restrict__ qhi, bf16* __restrict__ qlo)
{
    const int t = blockIdx.x, tid = threadIdx.x;
    __shared__ float cs[ROPEHS], sn[ROPEHS];
    if (tid < ROPEHS) {
        cs[tid] = cosT[(size_t)t * ROPEHS + tid];
        sn[tid] = sinT[(size_t)t * ROPEHS + tid];
    }
    __syncthreads();

    const float* lrow = lat + (size_t)t * LATD;
    bf16* krh = khi + (size_t)t * QKHS;
    bf16* krl = klo + (size_t)t * QKHS;
    for (int p = tid; p < QKHS / 2; p += 256) {
        int e = p * 2;
        float v[2];
        #pragma unroll
        for (int u = 0; u < 2; u++) {
            int ee = e + u;
            if (ee < KVLOW) v[u] = lrow[ee];
            else {
                int i2 = ee - KVLOW;
                float xv = lrow[ee];
                v[u] = (i2 < 32) ? xv * cs[i2] - lrow[ee + 32] * sn[i2]
                                 : xv * cs[i2] + lrow[ee - 32] * sn[i2];
            }
        }
        bf16 h0, l0, h1, l1;
        hlsplit(v[0], h0, l0); hlsplit(v[1], h1, l1);
        *(__nv_bfloat162*)(krh + e) = __nv_bfloat162(h0, h1);
        *(__nv_bfloat162*)(krl + e) = __nv_bfloat162(l0, l1);
    }

    const float* qrow = qbuf + (size_t)t * QTOT;
    bf16* qrh = qhi + (size_t)t * QTOT;
    bf16* qrl = qlo + (size_t)t * QTOT;
    for (int p = tid; p < QTOT / 2; p += 256) {
        int e = p * 2;
        float v[2];
        #pragma unroll
        for (int u = 0; u < 2; u++) {
            int ee = e + u;
            int hh = ee / QKHS;
            int i = ee - hh * QKHS;
            if (i < KVLOW) v[u] = qrow[ee];
            else {
                int i2 = i - KVLOW;
                float xv = qrow[ee];
                v[u] = (i2 < 32) ? xv * cs[i2] - qrow[ee + 32] * sn[i2]
                                 : xv * cs[i2] + qrow[ee - 32] * sn[i2];
            }
        }
        bf16 h0, l0, h1, l1;
        hlsplit(v[0], h0, l0); hlsplit(v[1], h1, l1);
        *(__nv_bfloat162*)(qrh + e) = __nv_bfloat162(h0, h1);
        *(__nv_bfloat162*)(qrl + e) = __nv_bfloat162(l0, l1);
    }
}

// ---------------- Softmax -> hi/lo attn (zero-filled to 128-boundary) ----------------
__global__ __launch_bounds__(256)
void softmax_kernel(const float* __restrict__ scores,
                    bf16* __restrict__ ahi, bf16* __restrict__ alo)
{
    __shared__ float srow[T_SEQ];
    __shared__ float red[8];
    const int t = blockIdx.x, h = blockIdx.y, tid = threadIdx.x;
    const float* row = scores + ((size_t)h * T_SEQ + t) * T_SEQ;
    const int n = t + 1;

    float m = -3.4e38f;
    for (int s = tid; s < n; s += 256) { float v = row[s]; srow[s] = v; m = fmaxf(m, v); }
    #pragma unroll
    for (int o = 16; o; o >>= 1) m = fmaxf(m, __shfl_xor_sync(0xffffffffu, m, o));
    if ((tid & 31) == 0) red[tid >> 5] = m;
    __syncthreads();
    float mmax = red[0];
    #pragma unroll
    for (int i = 1; i < 8; i++) mmax = fmaxf(mmax, red[i]);
    __syncthreads();

    float sum = 0.f;
    for (int s = tid; s < n; s += 256) { float e = __expf(srow[s] - mmax); srow[s] = e; sum += e; }
    #pragma unroll
    for (int o = 16; o; o >>= 1) sum += __shfl_xor_sync(0xffffffffu, sum, o);
    if ((tid & 31) == 0) red[tid >> 5] = sum;
    __syncthreads();
    float total = 0.f;
    #pragma unroll
    for (int i = 0; i < 8; i++) total += red[i];
    const float inv = 1.f / total;

    bf16* rh = ahi + ((size_t)h * T_SEQ + t) * T_SEQ;
    bf16* rl = alo + ((size_t)h * T_SEQ + t) * T_SEQ;
    const int kpad = ((t >> 7) + 1) << 7;   // 128-granular for PV K truncation
    for (int p = tid; p < (kpad >> 1); p += 256) {
        int s0 = 2 * p;
        float v0 = (s0 <= t) ? srow[s0] * inv : 0.f;
        float v1 = (s0 + 1 <= t) ? srow[s0 + 1] * inv : 0.f;
        bf16 h0, l0, h1, l1;
        hlsplit(v0, h0, l0); hlsplit(v1, h1, l1);
        *(__nv_bfloat162*)(rh + s0) = __nv_bfloat162(h0, h1);
        *(__nv_bfloat162*)(rl + s0) = __nv_bfloat162(l0, l1);
    }
}

// ---------------- mma.sync GEMM: C = alpha * A * B^T ----------------
// CTA tile 128x128, 256 threads (8 warps, 2m x 4n of 64x32), BK=32,
// 3-stage pipeline, compact XOR-swizzled smem, 1 sync/chunk, 2 CTAs/SM.
// Inner loop: product-major MMA ordering (16 independent MMAs per group)
// with LDSM issued between groups to hide smem latency.
#define TILEB  8192                 // 128 rows x 64B
#define STAGEB (4 * TILEB)          // 32768: Ahi, Alo, Bhi, Blo
#define NSTAGE 3
#define SMEM_TOT (NSTAGE * STAGEB)  // 98304

template<int CSKIP, bool CK, int EPI>   // EPI: 0 -> f32 C, 1 -> hi/lo bf16 C
__global__ __launch_bounds__(256, 2)
void mmagemm(const bf16* __restrict__ Ahi, const bf16* __restrict__ Alo,
             const bf16* __restrict__ Bhi, const bf16* __restrict__ Blo,
             float* __restrict__ Cf, bf16* __restrict__ Chi, bf16* __restrict__ Clo,
             int M, int N, int K, int ldA, int ldB, int ldC,
             long sA, long sB, long sC, float alpha)
{
    extern __shared__ char smc[];
    const int bx = blockIdx.x, by = blockIdx.y, z = blockIdx.z;
    if (CSKIP && bx > by) return;   // tile fully above causal diagonal

    Ahi += (size_t)z * sA;  Alo += (size_t)z * sA;
    Bhi += (size_t)z * sB;  Blo += (size_t)z * sB;

    const int Keff = CK ? min(K, (by + 1) * 128) : K;
    const int nc = Keff >> 5;
    const int tid = threadIdx.x, wid = tid >> 5, lane = tid & 31;
    const int m0 = by * 128, n0 = bx * 128;
    const uint32_t smb = smem_u32(smc);

    // ---- load mapping: thread -> row tid>>1, chunks {(tid&1)*2, (tid&1)*2+1} ----
    const int lrow = tid >> 1;
    const int lc0  = (tid & 1) * 2;                 // first 16B chunk index
    const int lswz = (lrow >> 1) & 3;
    const uint32_t dRow = (uint32_t)(lrow * 64);
    const uint32_t d0 = dRow + (uint32_t)((lc0 ^ lswz) << 4);
    const uint32_t d1 = dRow + (uint32_t)(((lc0 + 1) ^ lswz) << 4);
    const bf16* gAh = Ahi + (size_t)(m0 + lrow) * ldA + lc0 * 8;
    const bf16* gAl = Alo + (size_t)(m0 + lrow) * ldA + lc0 * 8;
    const bf16* gBh = Bhi + (size_t)(n0 + lrow) * ldB + lc0 * 8;
    const bf16* gBl = Blo + (size_t)(n0 + lrow) * ldB + lc0 * 8;

#define PREFETCH(c, s) do { \
        uint32_t b_ = smb + (uint32_t)(s) * STAGEB; \
        const bf16* p_ = gAh + (size_t)(c) * 32; \
        CPA(b_ + d0, p_); CPA(b_ + d1, p_ + 8); \
        p_ = gAl + (size_t)(c) * 32; \
        CPA(b_ + TILEB + d0, p_); CPA(b_ + TILEB + d1, p_ + 8); \
        p_ = gBh + (size_t)(c) * 32; \
        CPA(b_ + 2 * TILEB + d0, p_); CPA(b_ + 2 * TILEB + d1, p_ + 8); \
        p_ = gBl + (size_t)(c) * 32; \
        CPA(b_ + 3 * TILEB + d0, p_); CPA(b_ + 3 * TILEB + d1, p_ + 8); \
        CP_COMMIT(); \
    } while (0)

    // ---- compute mapping: warp tile 64x32 (2m x 4n warps) ----
    const int wm = (wid & 1) * 64;
    const int wn = (wid >> 1) * 32;
    // A: row = wm + mi*16 + (lane&15); 16B chunk = half*2 + (lane>>4)
    const int aRowL = lane & 15;
    const int aSwz = (aRowL >> 1) & 3;
    const int aCh = lane >> 4;
    const uint32_t aBase = (uint32_t)((wm + aRowL) * 64);
    // B: row = wn + nb*16 + (lane&7) + ((lane&16)>>1); chunk = half*2 + ((lane&8)>>3)
    const int bRowL = (lane & 7) + ((lane & 16) >> 1);
    const int bSwz = (bRowL >> 1) & 3;
    const int bCh = (lane & 8) >> 3;
    const uint32_t bBase = (uint32_t)((wn + bRowL) * 64);

    float acc[4][4][4];
    #pragma unroll
    for (int i = 0; i < 4; i++)
        #pragma unroll
        for (int j = 0; j < 4; j++)
            #pragma unroll
            for (int q = 0; q < 4; q++) acc[i][j][q] = 0.f;

    PREFETCH(0, 0);
    if (nc > 1) PREFETCH(1, 1);

    int st = 0;
    for (int c = 0; c < nc; ++c) {
        if (c + 1 < nc) CP_WAIT(1); else CP_WAIT(0);
        __syncthreads();
        if (c + 2 < nc) {
            int ps = st + 2; if (ps >= NSTAGE) ps -= NSTAGE;
            PREFETCH(c + 2, ps);
        }

        const uint32_t base = smb + (uint32_t)st * STAGEB;
        #pragma unroll
        for (int half = 0; half < 2; half++) {
            const uint32_t aCol = (uint32_t)(((half * 2 + aCh) ^ aSwz) << 4);
            const uint32_t bCol = (uint32_t)(((half * 2 + bCh) ^ bSwz) << 4);

            // Group 1 operands: ah, bh
            uint32_t ah[4][4];
            #pragma unroll
            for (int mi = 0; mi < 4; mi++)
                LDSM4(ah[mi], base + aBase + mi * 1024 + aCol);
            uint32_t bh[4][2];
            #pragma unroll
            for (int nb = 0; nb < 2; nb++) {
                uint32_t r4[4];
                LDSM4(r4, base + 2 * TILEB + bBase + nb * 1024 + bCol);
                bh[nb * 2][0] = r4[0]; bh[nb * 2][1] = r4[1];
                bh[nb * 2 + 1][0] = r4[2]; bh[nb * 2 + 1][1] = r4[3];
            }
            // Issue bl loads, then run P1 = ah*bh (16 independent MMAs)
            uint32_t bl[4][2];
            #pragma unroll
            for (int nb = 0; nb < 2; nb++) {
                uint32_t r4[4];
                LDSM4(r4, base + 3 * TILEB + bBase + nb * 1024 + bCol);
                bl[nb * 2][0] = r4[0]; bl[nb * 2][1] = r4[1];
                bl[nb * 2 + 1][0] = r4[2]; bl[nb * 2 + 1][1] = r4[3];
            }
            #pragma unroll
            for (int mi = 0; mi < 4; mi++)
                #pragma unroll
                for (int ni = 0; ni < 4; ni++)
                    MMA(acc[mi][ni], ah[mi], bh[ni]);

            // Issue al loads, then run P2 = ah*bl
            uint32_t al[4][4];
            #pragma unroll
            for (int mi = 0; mi < 4; mi++)
                LDSM4(al[mi], base + TILEB + aBase + mi * 1024 + aCol);
            #pragma unroll
            for (int mi = 0; mi < 4; mi++)
                #pragma unroll
                for (int ni = 0; ni < 4; ni++)
                    MMA(acc[mi][ni], ah[mi], bl[ni]);

            // P3 = al*bh
            #pragma unroll
            for (int mi = 0; mi < 4; mi++)
                #pragma unroll
                for (int ni = 0; ni < 4; ni++)
                    MMA(acc[mi][ni], al[mi], bh[ni]);
        }
        if (++st == NSTAGE) st = 0;
    }
#undef PREFETCH

    // ---- epilogue ----
    const int er = lane >> 2, ec = (lane & 3) * 2;
    if (EPI == 0) {
        float* Cz = Cf + (size_t)z * sC;
        #pragma unroll
        for (int mi = 0; mi < 4; mi++) {
            const int r1 = m0 + wm + mi * 16 + er;
            #pragma unroll
            for (int ni = 0; ni < 4; ni++) {
                const int c1 = n0 + wn + ni * 8 + ec;
                if (c1 < N) {
                    float2 v0 = make_float2(acc[mi][ni][0] * alpha, acc[mi][ni][1] * alpha);
                    float2 v1 = make_float2(acc[mi][ni][2] * alpha, acc[mi][ni][3] * alpha);
                    *(float2*)(Cz + (size_t)r1 * ldC + c1) = v0;
                    *(float2*)(Cz + (size_t)(r1 + 8) * ldC + c1) = v1;
                }
            }
        }
    } else {
        bf16* Ch = Chi + (size_t)z * sC;
        bf16* Cl = Clo + (size_t)z * sC;
        #pragma unroll
        for (int mi = 0; mi < 4; mi++) {
            const int r1 = m0 + wm + mi * 16 + er;
            #pragma unroll
            for (int ni = 0; ni < 4; ni++) {
                const int c1 = n0 + wn + ni * 8 + ec;
                if (c1 < N) {
                    bf16 h0, l0, h1, l1;
                    hlsplit(acc[mi][ni][0] * alpha, h0, l0);
                    hlsplit(acc[mi][ni][1] * alpha, h1, l1);
                    *(__nv_bfloat162*)(Ch + (size_t)r1 * ldC + c1) = __nv_bfloat162(h0, h1);
                    *(__nv_bfloat162*)(Cl + (size_t)r1 * ldC + c1) = __nv_bfloat162(l0, l1);
                    hlsplit(acc[mi][ni][2] * alpha, h0, l0);
                    hlsplit(acc[mi][ni][3] * alpha, h1, l1);
                    *(__nv_bfloat162*)(Ch + (size_t)(r1 + 8) * ldC + c1) = __nv_bfloat162(h0, h1);
                    *(__nv_bfloat162*)(Cl + (size_t)(r1 + 8) * ldC + c1) = __nv_bfloat162(l0, l1);
                }
            }
        }
    }
}

// ---------------- Launch ----------------
extern "C" void kernel_launch(void* const* d_in, const int* in_sizes, int n_in,
                              void* d_out, int out_size)
{
    (void)in_sizes; (void)n_in; (void)out_size;
    const float* x     = (const float*)d_in[0];
    const float* cosT  = (const float*)d_in[1];
    const float* sinT  = (const float*)d_in[2];
    const float* Wqkv  = (const float*)d_in[3];
    const float* Wqdec = (const float*)d_in[4];
    const float* Wout  = (const float*)d_in[5];
    float* out = (float*)d_out;

    float *lat, *qbuf, *scores;
    bf16 *xhi, *xlo, *wqkvThi, *wqkvTlo, *cqhi, *cqlo, *wqdecThi, *wqdecTlo;
    bf16 *qhi, *qlo, *khi, *klo, *vThi, *vTlo, *attnhi, *attnlo, *yhi, *ylo, *woutThi, *woutTlo;
    cudaGetSymbolAddress((void**)&lat, g_lat);
    cudaGetSymbolAddress((void**)&qbuf, g_qbuf);
    cudaGetSymbolAddress((void**)&scores, g_scores);
    cudaGetSymbolAddress((void**)&xhi, g_xhi);       cudaGetSymbolAddress((void**)&xlo, g_xlo);
    cudaGetSymbolAddress((void**)&wqkvThi, g_wqkvThi); cudaGetSymbolAddress((void**)&wqkvTlo, g_wqkvTlo);
    cudaGetSymbolAddress((void**)&cqhi, g_cqhi);     cudaGetSymbolAddress((void**)&cqlo, g_cqlo);
    cudaGetSymbolAddress((void**)&wqdecThi, g_wqdecThi); cudaGetSymbolAddress((void**)&wqdecTlo, g_wqdecTlo);
    cudaGetSymbolAddress((void**)&qhi, g_qhi);       cudaGetSymbolAddress((void**)&qlo, g_qlo);
    cudaGetSymbolAddress((void**)&khi, g_khi);       cudaGetSymbolAddress((void**)&klo, g_klo);
    cudaGetSymbolAddress((void**)&vThi, g_vThi);     cudaGetSymbolAddress((void**)&vTlo, g_vTlo);
    cudaGetSymbolAddress((void**)&attnhi, g_attnhi); cudaGetSymbolAddress((void**)&attnlo, g_attnlo);
    cudaGetSymbolAddress((void**)&yhi, g_yhi);       cudaGetSymbolAddress((void**)&ylo, g_ylo);
    cudaGetSymbolAddress((void**)&woutThi, g_woutThi); cudaGetSymbolAddress((void**)&woutTlo, g_woutTlo);

    cudaFuncSetAttribute((const void*)mmagemm<0, false, 0>,
                         cudaFuncAttributeMaxDynamicSharedMemorySize, SMEM_TOT);
    cudaFuncSetAttribute((const void*)mmagemm<1, false, 0>,
                         cudaFuncAttributeMaxDynamicSharedMemorySize, SMEM_TOT);
    cudaFuncSetAttribute((const void*)mmagemm<0, true, 1>,
                         cudaFuncAttributeMaxDynamicSharedMemorySize, SMEM_TOT);

    const float scale = 0.04419417382415922f;   // 1/sqrt(512)

    // 0-2: input conversions
    conv_x<<<8192, 256>>>(x, xhi, xlo);
    conv_wqkv<<<dim3(NPAD1 / 32, NEMBD / 32), 256>>>(Wqkv, wqkvThi, wqkvTlo);
    conv_w2<<<NQDBLK + NWOBLK, 256>>>(Wqdec, wqdecThi, wqdecTlo, Wout, woutThi, woutTlo);

    // 3: G1: lat = x @ Wqkv  [2048 x 1600]
    mmagemm<0, false, 0><<<dim3(13, 16, 1), 256, SMEM_TOT>>>(
        xhi, xlo, wqkvThi, wqkvTlo, lat, nullptr, nullptr,
        T_SEQ, LATD, NEMBD, NEMBD, NEMBD, LATD, 0, 0, 0, 1.f);

    // 4: conversions from lat (fused)
    conv_lat<<<NCQBLK + NVTBLK, 256>>>(lat, cqhi, cqlo, vThi, vTlo);

    // 5: G2: qbuf = c_q @ Wqdec  [2048 x 9216]
    mmagemm<0, false, 0><<<dim3(72, 16, 1), 256, SMEM_TOT>>>(
        cqhi, cqlo, wqdecThi, wqdecTlo, qbuf, nullptr, nullptr,
        T_SEQ, QTOT, QLOW, QLOW, QLOW, QTOT, 0, 0, 0, 1.f);

    // 6: RoPE + hi/lo q/k
    rope_pack_kernel<<<T_SEQ, 256>>>(lat, qbuf, cosT, sinT, khi, klo, qhi, qlo);

    // 7: scores[h] = scale * q_h @ k^T, causal tile skip
    mmagemm<1, false, 0><<<dim3(16, 16, NHEAD), 256, SMEM_TOT>>>(
        qhi, qlo, khi, klo, scores, nullptr, nullptr,
        T_SEQ, T_SEQ, QKHS, QTOT, QKHS, T_SEQ,
        (long)QKHS, 0, (long)T_SEQ * T_SEQ, scale);

    // 8: softmax -> hi/lo attn
    softmax_kernel<<<dim3(T_SEQ, NHEAD), 256>>>(scores, attnhi, attnlo);

    // 9: PV: y_h = attn_h @ v (K causal-truncated), bf16 hi/lo epilogue
    mmagemm<0, true, 1><<<dim3(4, 16, NHEAD), 256, SMEM_TOT>>>(
        attnhi, attnlo, vThi, vTlo, nullptr, yhi, ylo,
        T_SEQ, KVLOW, T_SEQ, T_SEQ, T_SEQ, YTOT,
        (long)T_SEQ * T_SEQ, 0, (long)KVLOW, 1.f);

    // 10: G3: out = y @ Wout  [2048 x 2048]
    mmagemm<0, false, 0><<<dim3(16, 16, 1), 256, SMEM_TOT>>>(
        yhi, ylo, woutThi, woutTlo, out, nullptr, nullptr,
        T_SEQ, NEMBD, YTOT, YTOT, YTOT, NEMBD, 0, 0, 0, 1.f);
}